// round 1
// baseline (speedup 1.0000x reference)
#include <cuda_runtime.h>

#define NN   8192
#define CC   128
#define KNBR 7
#define BQ   64
#define BK   64

// ---------------- device scratch (no allocations allowed) ----------------
__device__ float g_q[NN * CC];
__device__ float g_k[NN * CC];
__device__ float g_v[NN * CC];
__device__ float g_skip[NN * CC];
__device__ float g_h[NN * CC];
__device__ float g_norm[NN];          // 0.5*|h|^2
__device__ int   g_idx[NN * KNBR];
__device__ float g_m1[NN * CC];
__device__ float g_h1[NN * CC];
__device__ float g_m2[NN];

// ---------------- K1: fused projections q,k,v,skip ----------------
__global__ __launch_bounds__(256) void proj_kernel(
    const float* __restrict__ x,
    const float* __restrict__ Wq, const float* __restrict__ bq,
    const float* __restrict__ Wk, const float* __restrict__ bk,
    const float* __restrict__ Wv, const float* __restrict__ bv,
    const float* __restrict__ Ws, const float* __restrict__ bs)
{
    __shared__ float xs[32 * 129];
    const int tid = threadIdx.x;
    const int r0  = blockIdx.x * 32;

    for (int i = tid; i < 32 * CC; i += 256) {
        int r = i >> 7, c = i & 127;
        xs[r * 129 + c] = x[(r0 + r) * CC + c];
    }
    __syncthreads();

    const int ri = (tid >> 5) * 4;     // 8 row-groups of 4
    const int c0 = (tid & 31) * 4;     // 32 col-groups of 4

    const float* Wt[4] = {Wq, Wk, Wv, Ws};
    const float* bt[4] = {bq, bk, bv, bs};
    float* Ot[4];
    Ot[0] = g_q; Ot[1] = g_k; Ot[2] = g_v; Ot[3] = g_skip;

    #pragma unroll
    for (int w = 0; w < 4; w++) {
        const float* W = Wt[w];
        float acc[4][4];
        #pragma unroll
        for (int i = 0; i < 4; i++)
            #pragma unroll
            for (int j = 0; j < 4; j++) acc[i][j] = 0.f;

        for (int k2 = 0; k2 < CC; k2++) {
            float4 wv = *reinterpret_cast<const float4*>(W + k2 * CC + c0);
            #pragma unroll
            for (int dr = 0; dr < 4; dr++) {
                float xv = xs[(ri + dr) * 129 + k2];
                acc[dr][0] += xv * wv.x;
                acc[dr][1] += xv * wv.y;
                acc[dr][2] += xv * wv.z;
                acc[dr][3] += xv * wv.w;
            }
        }
        float4 bb = *reinterpret_cast<const float4*>(bt[w] + c0);
        #pragma unroll
        for (int dr = 0; dr < 4; dr++) {
            float4 o;
            o.x = acc[dr][0] + bb.x;
            o.y = acc[dr][1] + bb.y;
            o.z = acc[dr][2] + bb.z;
            o.w = acc[dr][3] + bb.w;
            *reinterpret_cast<float4*>(Ot[w] + (r0 + ri + dr) * CC + c0) = o;
        }
    }
}

// ---------------- K2: flash attention + skip, writes g_h ----------------
// smem floats: qs 64*129, ks 64*129, vs 64*129, Ps 64*65, mrow/lrow/srow 64 each
#define ATTN_SMEM_FLOATS (3 * BQ * 129 + BQ * 65 + 3 * BQ)

__global__ __launch_bounds__(256, 1) void attn_kernel()
{
    extern __shared__ float sm[];
    float* qs   = sm;
    float* ks   = qs + BQ * 129;
    float* vs   = ks + BK * 129;
    float* Ps   = vs + BK * 129;          // stride 65
    float* mrow = Ps + BQ * 65;
    float* lrow = mrow + BQ;
    float* srow = lrow + BQ;

    const int tid   = threadIdx.x;
    const int qbase = blockIdx.x * BQ;
    const float scale = 0.08838834764831843f;   // 1/sqrt(128)

    for (int i = tid; i < BQ * CC; i += 256) {
        int r = i >> 7, c = i & 127;
        qs[r * 129 + c] = g_q[(qbase + r) * CC + c] * scale;
    }
    if (tid < BQ) { mrow[tid] = -1e30f; lrow[tid] = 0.f; }

    const int si0 = (tid >> 4) * 4;   // score rows
    const int sj0 = (tid & 15) * 4;   // score cols
    const int pr0 = si0;              // PV rows
    const int pc  = tid & 15;         // PV col base (strided by 16)

    float acc[4][8];
    #pragma unroll
    for (int i = 0; i < 4; i++)
        #pragma unroll
        for (int j = 0; j < 8; j++) acc[i][j] = 0.f;

    for (int kb = 0; kb < NN; kb += BK) {
        __syncthreads();
        for (int i = tid; i < BK * CC; i += 256) {
            int r = i >> 7, c = i & 127;
            ks[r * 129 + c] = g_k[(kb + r) * CC + c];
            vs[r * 129 + c] = g_v[(kb + r) * CC + c];
        }
        __syncthreads();

        // ---- scores S = (q*scale) @ k^T, 4x4 register tile ----
        float s[4][4];
        #pragma unroll
        for (int i = 0; i < 4; i++)
            #pragma unroll
            for (int j = 0; j < 4; j++) s[i][j] = 0.f;

        for (int k2 = 0; k2 < CC; k2++) {
            float q4[4], k4[4];
            #pragma unroll
            for (int d = 0; d < 4; d++) q4[d] = qs[(si0 + d) * 129 + k2];
            #pragma unroll
            for (int d = 0; d < 4; d++) k4[d] = ks[(sj0 + d) * 129 + k2];
            #pragma unroll
            for (int di = 0; di < 4; di++)
                #pragma unroll
                for (int dj = 0; dj < 4; dj++) s[di][dj] += q4[di] * k4[dj];
        }
        #pragma unroll
        for (int di = 0; di < 4; di++)
            #pragma unroll
            for (int dj = 0; dj < 4; dj++) {
                float v = s[di][dj];
                if (qbase + si0 + di == kb + sj0 + dj) v = -1e30f;  // mask diag
                Ps[(si0 + di) * 65 + sj0 + dj] = v;
            }
        __syncthreads();

        // ---- per-row online softmax stats (deterministic, one thread/row) ----
        if (tid < BQ) {
            float mo = mrow[tid];
            float mx = mo;
            for (int j = 0; j < BK; j++) mx = fmaxf(mx, Ps[tid * 65 + j]);
            float sum = 0.f;
            for (int j = 0; j < BK; j++) {
                float e = __expf(Ps[tid * 65 + j] - mx);
                Ps[tid * 65 + j] = e;
                sum += e;
            }
            float sc = __expf(mo - mx);
            mrow[tid] = mx;
            srow[tid] = sc;
            lrow[tid] = lrow[tid] * sc + sum;
        }
        __syncthreads();

        // ---- PV accumulate with rescale ----
        float scr[4];
        #pragma unroll
        for (int d = 0; d < 4; d++) scr[d] = srow[pr0 + d];
        #pragma unroll
        for (int d = 0; d < 4; d++)
            #pragma unroll
            for (int cc = 0; cc < 8; cc++) acc[d][cc] *= scr[d];

        for (int j = 0; j < BK; j++) {
            float p4[4];
            #pragma unroll
            for (int d = 0; d < 4; d++) p4[d] = Ps[(pr0 + d) * 65 + j];
            #pragma unroll
            for (int cc = 0; cc < 8; cc++) {
                float vv = vs[j * 129 + pc + 16 * cc];
                #pragma unroll
                for (int d = 0; d < 4; d++) acc[d][cc] += p4[d] * vv;
            }
        }
    }
    __syncthreads();

    #pragma unroll
    for (int d = 0; d < 4; d++) {
        int gr = qbase + pr0 + d;
        float inv = 1.f / lrow[pr0 + d];
        #pragma unroll
        for (int cc = 0; cc < 8; cc++) {
            int c = pc + 16 * cc;
            g_h[gr * CC + c] = acc[d][cc] * inv + g_skip[gr * CC + c];
        }
    }
}

// ---------------- K3: row norms 0.5*|h|^2 ----------------
__global__ __launch_bounds__(256) void norm_kernel()
{
    int row  = blockIdx.x * 8 + (threadIdx.x >> 5);
    int lane = threadIdx.x & 31;
    const float* h = g_h + row * CC;
    float s = 0.f;
    for (int c = lane; c < CC; c += 32) { float v = h[c]; s += v * v; }
    s += __shfl_xor_sync(0xffffffffu, s, 16);
    s += __shfl_xor_sync(0xffffffffu, s, 8);
    s += __shfl_xor_sync(0xffffffffu, s, 4);
    s += __shfl_xor_sync(0xffffffffu, s, 2);
    s += __shfl_xor_sync(0xffffffffu, s, 1);
    if (lane == 0) g_norm[row] = 0.5f * s;
}

// ---------------- K4: kNN (top-7 of h_i.h_j - 0.5|h_j|^2, j != i) ----------------
#define KNN_SMEM_FLOATS (2 * BQ * 129 + BQ * 65 + BQ)

__global__ __launch_bounds__(256, 1) void knn_kernel()
{
    extern __shared__ float sm[];
    float* qs = sm;
    float* ks = qs + BQ * 129;
    float* Ps = ks + BK * 129;   // stride 65
    float* nr = Ps + BQ * 65;

    const int tid   = threadIdx.x;
    const int qbase = blockIdx.x * BQ;

    for (int i = tid; i < BQ * CC; i += 256) {
        int r = i >> 7, c = i & 127;
        qs[r * 129 + c] = g_h[(qbase + r) * CC + c];
    }

    const int si0 = (tid >> 4) * 4;
    const int sj0 = (tid & 15) * 4;

    float bestv[KNBR];
    int   besti[KNBR];
    #pragma unroll
    for (int t = 0; t < KNBR; t++) { bestv[t] = -1e30f; besti[t] = 0; }
    float vmin = -1e30f;

    for (int kb = 0; kb < NN; kb += BK) {
        __syncthreads();
        for (int i = tid; i < BK * CC; i += 256) {
            int r = i >> 7, c = i & 127;
            ks[r * 129 + c] = g_h[(kb + r) * CC + c];
        }
        if (tid < BK) nr[tid] = g_norm[kb + tid];
        __syncthreads();

        float s[4][4];
        #pragma unroll
        for (int i = 0; i < 4; i++)
            #pragma unroll
            for (int j = 0; j < 4; j++) s[i][j] = 0.f;

        for (int k2 = 0; k2 < CC; k2++) {
            float q4[4], k4[4];
            #pragma unroll
            for (int d = 0; d < 4; d++) q4[d] = qs[(si0 + d) * 129 + k2];
            #pragma unroll
            for (int d = 0; d < 4; d++) k4[d] = ks[(sj0 + d) * 129 + k2];
            #pragma unroll
            for (int di = 0; di < 4; di++)
                #pragma unroll
                for (int dj = 0; dj < 4; dj++) s[di][dj] += q4[di] * k4[dj];
        }
        #pragma unroll
        for (int di = 0; di < 4; di++)
            #pragma unroll
            for (int dj = 0; dj < 4; dj++) {
                float v = s[di][dj] - nr[sj0 + dj];
                if (qbase + si0 + di == kb + sj0 + dj) v = -1e30f;  // exclude self
                Ps[(si0 + di) * 65 + sj0 + dj] = v;
            }
        __syncthreads();

        if (tid < BQ) {
            for (int j = 0; j < BK; j++) {
                float v = Ps[tid * 65 + j];
                if (v > vmin) {
                    int p = KNBR - 1;
                    while (p > 0 && v > bestv[p - 1]) {
                        bestv[p] = bestv[p - 1];
                        besti[p] = besti[p - 1];
                        p--;
                    }
                    bestv[p] = v;
                    besti[p] = kb + j;
                    vmin = bestv[KNBR - 1];
                }
            }
        }
        // Ps/ks reused only after the loop-top __syncthreads()
    }

    if (tid < BQ) {
        #pragma unroll
        for (int t = 0; t < KNBR; t++)
            g_idx[(qbase + tid) * KNBR + t] = besti[t];
    }
}

// ---------------- K5: m1 = h @ W1 (no bias) ----------------
__global__ __launch_bounds__(256) void gcn1_gemm(const float* __restrict__ W1)
{
    __shared__ float xs[32 * 129];
    const int tid = threadIdx.x;
    const int r0  = blockIdx.x * 32;

    for (int i = tid; i < 32 * CC; i += 256) {
        int r = i >> 7, c = i & 127;
        xs[r * 129 + c] = g_h[(r0 + r) * CC + c];
    }
    __syncthreads();

    const int ri = (tid >> 5) * 4;
    const int c0 = (tid & 31) * 4;

    float acc[4][4];
    #pragma unroll
    for (int i = 0; i < 4; i++)
        #pragma unroll
        for (int j = 0; j < 4; j++) acc[i][j] = 0.f;

    for (int k2 = 0; k2 < CC; k2++) {
        float4 wv = *reinterpret_cast<const float4*>(W1 + k2 * CC + c0);
        #pragma unroll
        for (int dr = 0; dr < 4; dr++) {
            float xv = xs[(ri + dr) * 129 + k2];
            acc[dr][0] += xv * wv.x;
            acc[dr][1] += xv * wv.y;
            acc[dr][2] += xv * wv.z;
            acc[dr][3] += xv * wv.w;
        }
    }
    #pragma unroll
    for (int dr = 0; dr < 4; dr++) {
        float4 o;
        o.x = acc[dr][0]; o.y = acc[dr][1]; o.z = acc[dr][2]; o.w = acc[dr][3];
        *reinterpret_cast<float4*>(g_m1 + (r0 + ri + dr) * CC + c0) = o;
    }
}

// ---------------- K6: GCN layer-1 gather + relu ----------------
__global__ __launch_bounds__(128) void gather1(const float* __restrict__ b1)
{
    int node = blockIdx.x;
    int c    = threadIdx.x;
    float s = g_m1[node * CC + c];
    #pragma unroll
    for (int t = 0; t < KNBR; t++) {
        int nb = g_idx[node * KNBR + t];
        s += g_m1[nb * CC + c];
    }
    g_h1[node * CC + c] = fmaxf(s * 0.125f + b1[c], 0.f);
}

// ---------------- K7: m2 = h1 @ W2 (OUT_C = 1) ----------------
__global__ __launch_bounds__(256) void m2_kernel(const float* __restrict__ W2)
{
    int row  = blockIdx.x * 8 + (threadIdx.x >> 5);
    int lane = threadIdx.x & 31;
    float s = 0.f;
    for (int c = lane; c < CC; c += 32) s += g_h1[row * CC + c] * W2[c];
    s += __shfl_xor_sync(0xffffffffu, s, 16);
    s += __shfl_xor_sync(0xffffffffu, s, 8);
    s += __shfl_xor_sync(0xffffffffu, s, 4);
    s += __shfl_xor_sync(0xffffffffu, s, 2);
    s += __shfl_xor_sync(0xffffffffu, s, 1);
    if (lane == 0) g_m2[row] = s;
}

// ---------------- K8: GCN layer-2 gather -> output ----------------
__global__ __launch_bounds__(256) void out_kernel(const float* __restrict__ b2,
                                                  float* __restrict__ out)
{
    int n = blockIdx.x * 256 + threadIdx.x;
    float s = g_m2[n];
    #pragma unroll
    for (int t = 0; t < KNBR; t++) s += g_m2[g_idx[n * KNBR + t]];
    out[n] = s * 0.125f + b2[0];
}

// ---------------- launch ----------------
extern "C" void kernel_launch(void* const* d_in, const int* in_sizes, int n_in,
                              void* d_out, int out_size)
{
    const float* x   = (const float*)d_in[0];
    const float* Wq  = (const float*)d_in[1];
    const float* bq  = (const float*)d_in[2];
    const float* Wk  = (const float*)d_in[3];
    const float* bk  = (const float*)d_in[4];
    const float* Wv  = (const float*)d_in[5];
    const float* bv  = (const float*)d_in[6];
    const float* Wsk = (const float*)d_in[7];
    const float* bsk = (const float*)d_in[8];
    const float* W1  = (const float*)d_in[9];
    const float* b1  = (const float*)d_in[10];
    const float* W2  = (const float*)d_in[11];
    const float* b2  = (const float*)d_in[12];
    float* out = (float*)d_out;

    const int attn_smem = ATTN_SMEM_FLOATS * (int)sizeof(float);  // 116480 B
    const int knn_smem  = KNN_SMEM_FLOATS  * (int)sizeof(float);  //  82944 B
    cudaFuncSetAttribute(attn_kernel, cudaFuncAttributeMaxDynamicSharedMemorySize, attn_smem);
    cudaFuncSetAttribute(knn_kernel,  cudaFuncAttributeMaxDynamicSharedMemorySize, knn_smem);

    proj_kernel<<<NN / 32, 256>>>(x, Wq, bq, Wk, bk, Wv, bv, Wsk, bsk);
    attn_kernel<<<NN / BQ, 256, attn_smem>>>();
    norm_kernel<<<NN / 8, 256>>>();
    knn_kernel<<<NN / BQ, 256, knn_smem>>>();
    gcn1_gemm<<<NN / 32, 256>>>(W1);
    gather1<<<NN, CC>>>(b1);
    m2_kernel<<<NN / 8, 256>>>(W2);
    out_kernel<<<NN / 256, 256>>>(b2, out);
}

// round 2
// speedup vs baseline: 1.4963x; 1.4963x over previous
#include <cuda_runtime.h>

#define NN   8192
#define CC   128
#define KNBR 7
#define S2   132          // smem row stride (floats), 16B-aligned, odd-bank-ish
#define HALFN 4096

typedef unsigned long long ull;

// ---------------- device scratch (no allocations allowed) ----------------
__device__ float g_q[NN * CC];
__device__ float g_k[NN * CC];
__device__ float g_v[NN * CC];
__device__ float g_skip[NN * CC];
__device__ float g_h[NN * CC];
__device__ float g_acc[2 * NN * CC];   // attention partial numerators per half
__device__ float g_l[2 * NN];          // partial denominators per half
__device__ float g_norm[NN];           // 0.5*|h|^2
__device__ float g_cv[2 * NN * KNBR];  // per-half top-7 values
__device__ int   g_ci[2 * NN * KNBR];  // per-half top-7 indices
__device__ int   g_idx[NN * KNBR];
__device__ float g_m1[NN * CC];
__device__ float g_h1[NN * CC];
__device__ float g_m2[NN];

// ---------------- packed fp32x2 helpers ----------------
__device__ __forceinline__ ull ffma2(ull a, ull b, ull c) {
    ull d;
    asm("fma.rn.f32x2 %0, %1, %2, %3;" : "=l"(d) : "l"(a), "l"(b), "l"(c));
    return d;
}
__device__ __forceinline__ ull dup2(float x) {
    ull d;
    asm("mov.b64 %0, {%1, %1};" : "=l"(d) : "f"(x));
    return d;
}
__device__ __forceinline__ float2 upk(ull v) {
    float2 r;
    asm("mov.b64 {%0, %1}, %2;" : "=f"(r.x), "=f"(r.y) : "l"(v));
    return r;
}

// ---------------- K1: fused projections q,k,v,skip (f32x2 packed) ----------------
__global__ __launch_bounds__(256) void proj_kernel(
    const float* __restrict__ x,
    const float* __restrict__ Wq, const float* __restrict__ bq,
    const float* __restrict__ Wk, const float* __restrict__ bk,
    const float* __restrict__ Wv, const float* __restrict__ bv,
    const float* __restrict__ Ws, const float* __restrict__ bs)
{
    __shared__ float xs[32 * 129];
    const int tid = threadIdx.x;
    const int r0  = blockIdx.x * 32;

    for (int i = tid; i < 32 * CC; i += 256) {
        int r = i >> 7, c = i & 127;
        xs[r * 129 + c] = x[(r0 + r) * CC + c];
    }
    __syncthreads();

    const int ri = (tid >> 5) * 4;
    const int c0 = (tid & 31) * 4;

    const float* Wt[4] = {Wq, Wk, Wv, Ws};
    const float* bt[4] = {bq, bk, bv, bs};
    float* Ot[4];
    Ot[0] = g_q; Ot[1] = g_k; Ot[2] = g_v; Ot[3] = g_skip;

    #pragma unroll
    for (int w = 0; w < 4; w++) {
        const float* W = Wt[w];
        ull acc[4][2];
        #pragma unroll
        for (int i = 0; i < 4; i++) { acc[i][0] = 0ULL; acc[i][1] = 0ULL; }

        #pragma unroll 4
        for (int k2 = 0; k2 < CC; k2++) {
            ulonglong2 wp = *reinterpret_cast<const ulonglong2*>(W + k2 * CC + c0);
            #pragma unroll
            for (int dr = 0; dr < 4; dr++) {
                ull x2 = dup2(xs[(ri + dr) * 129 + k2]);
                acc[dr][0] = ffma2(x2, wp.x, acc[dr][0]);
                acc[dr][1] = ffma2(x2, wp.y, acc[dr][1]);
            }
        }
        float4 bb = *reinterpret_cast<const float4*>(bt[w] + c0);
        #pragma unroll
        for (int dr = 0; dr < 4; dr++) {
            float2 a0 = upk(acc[dr][0]), a1 = upk(acc[dr][1]);
            float4 o;
            o.x = a0.x + bb.x; o.y = a0.y + bb.y;
            o.z = a1.x + bb.z; o.w = a1.y + bb.w;
            *reinterpret_cast<float4*>(Ot[w] + (r0 + ri + dr) * CC + c0) = o;
        }
    }
}

// ---------------- K2: flash attention, split over 2 key halves ----------------
// smem: qsT[128][S2] + kv[128][S2] + Ps[128][S2] + lrow[128]
#define BIG_SMEM_FLOATS (3 * 128 * S2 + 128)

__global__ __launch_bounds__(256, 1) void attn2_kernel()
{
    extern __shared__ float sm[];
    float* qsT  = sm;                    // k-major: qsT[k2][r]
    float* kv   = qsT + 128 * S2;        // score: ksT[k2][c]; PV: vs[j][c]
    float* Ps   = kv  + 128 * S2;        // Ps[r][j]
    float* lrow = Ps  + 128 * S2;        // [128]

    const int tid   = threadIdx.x;
    const int qbase = blockIdx.x * 128;
    const int kofs  = blockIdx.y * HALFN;
    const float scale = 0.08838834764831843f;   // 1/sqrt(128)

    const int ti = tid >> 4, tj = tid & 15;
    const int r0 = ti * 8,   c0 = tj * 8;

    // load Q transposed + scaled (once)
    for (int idx = tid; idx < 4096; idx += 256) {
        int r = idx & 127, c4 = (idx >> 7) << 2;
        float4 v = *reinterpret_cast<const float4*>(&g_q[(qbase + r) * CC + c4]);
        qsT[(c4 + 0) * S2 + r] = v.x * scale;
        qsT[(c4 + 1) * S2 + r] = v.y * scale;
        qsT[(c4 + 2) * S2 + r] = v.z * scale;
        qsT[(c4 + 3) * S2 + r] = v.w * scale;
    }
    if (tid < 128) lrow[tid] = 0.f;

    ull pv[8][4];
    #pragma unroll
    for (int d = 0; d < 8; d++)
        #pragma unroll
        for (int e = 0; e < 4; e++) pv[d][e] = 0ULL;

    for (int kb = 0; kb < HALFN; kb += 128) {
        __syncthreads();
        // load K transposed: ksT[k2][j]
        for (int idx = tid; idx < 4096; idx += 256) {
            int j = idx & 127, c4 = (idx >> 7) << 2;
            float4 v = *reinterpret_cast<const float4*>(&g_k[(kofs + kb + j) * CC + c4]);
            kv[(c4 + 0) * S2 + j] = v.x;
            kv[(c4 + 1) * S2 + j] = v.y;
            kv[(c4 + 2) * S2 + j] = v.z;
            kv[(c4 + 3) * S2 + j] = v.w;
        }
        __syncthreads();

        // ---- scores: 8x8 register tile, packed fp32x2 ----
        ull acc[8][4];
        #pragma unroll
        for (int d = 0; d < 8; d++)
            #pragma unroll
            for (int e = 0; e < 4; e++) acc[d][e] = 0ULL;

        #pragma unroll 4
        for (int k2 = 0; k2 < 128; k2++) {
            float4 qa  = *reinterpret_cast<const float4*>(&qsT[k2 * S2 + r0]);
            float4 qb4 = *reinterpret_cast<const float4*>(&qsT[k2 * S2 + r0 + 4]);
            ulonglong2 ka  = *reinterpret_cast<const ulonglong2*>(&kv[k2 * S2 + c0]);
            ulonglong2 kb2 = *reinterpret_cast<const ulonglong2*>(&kv[k2 * S2 + c0 + 4]);
            float qf[8] = {qa.x, qa.y, qa.z, qa.w, qb4.x, qb4.y, qb4.z, qb4.w};
            #pragma unroll
            for (int d = 0; d < 8; d++) {
                ull qd = dup2(qf[d]);
                acc[d][0] = ffma2(qd, ka.x,  acc[d][0]);
                acc[d][1] = ffma2(qd, ka.y,  acc[d][1]);
                acc[d][2] = ffma2(qd, kb2.x, acc[d][2]);
                acc[d][3] = ffma2(qd, kb2.y, acc[d][3]);
            }
        }

        // ---- exp (no max subtraction: scores bounded ~|5.8|), mask diag ----
        float lp[8];
        #pragma unroll
        for (int d = 0; d < 8; d++) {
            int gr = qbase + r0 + d;
            float ev[8];
            #pragma unroll
            for (int e2 = 0; e2 < 4; e2++) {
                float2 s = upk(acc[d][e2]);
                int gc = kofs + kb + c0 + 2 * e2;
                float s0 = (gr == gc)     ? -1e30f : s.x;
                float s1 = (gr == gc + 1) ? -1e30f : s.y;
                ev[2 * e2]     = __expf(s0);
                ev[2 * e2 + 1] = __expf(s1);
            }
            lp[d] = ((ev[0] + ev[1]) + (ev[2] + ev[3])) +
                    ((ev[4] + ev[5]) + (ev[6] + ev[7]));
            float4 o1 = {ev[0], ev[1], ev[2], ev[3]};
            float4 o2 = {ev[4], ev[5], ev[6], ev[7]};
            *reinterpret_cast<float4*>(&Ps[(r0 + d) * S2 + c0])     = o1;
            *reinterpret_cast<float4*>(&Ps[(r0 + d) * S2 + c0 + 4]) = o2;
        }
        #pragma unroll
        for (int m = 1; m <= 8; m <<= 1)
            #pragma unroll
            for (int d = 0; d < 8; d++)
                lp[d] += __shfl_xor_sync(0xffffffffu, lp[d], m);
        if (tj == 0)
            #pragma unroll
            for (int d = 0; d < 8; d++) lrow[r0 + d] += lp[d];
        __syncthreads();

        // load V (j-major) into same buffer
        for (int idx = tid; idx < 4096; idx += 256) {
            int j = idx >> 5, c4 = (idx & 31) << 2;
            float4 v = *reinterpret_cast<const float4*>(&g_v[(kofs + kb + j) * CC + c4]);
            *reinterpret_cast<float4*>(&kv[j * S2 + c4]) = v;
        }
        __syncthreads();

        // ---- PV accumulate ----
        #pragma unroll 2
        for (int j = 0; j < 128; j++) {
            ulonglong2 va = *reinterpret_cast<const ulonglong2*>(&kv[j * S2 + c0]);
            ulonglong2 vb = *reinterpret_cast<const ulonglong2*>(&kv[j * S2 + c0 + 4]);
            #pragma unroll
            for (int d = 0; d < 8; d++) {
                ull pd = dup2(Ps[(r0 + d) * S2 + j]);
                pv[d][0] = ffma2(pd, va.x, pv[d][0]);
                pv[d][1] = ffma2(pd, va.y, pv[d][1]);
                pv[d][2] = ffma2(pd, vb.x, pv[d][2]);
                pv[d][3] = ffma2(pd, vb.y, pv[d][3]);
            }
        }
    }

    float* aout = g_acc + (size_t)blockIdx.y * NN * CC;
    #pragma unroll
    for (int d = 0; d < 8; d++) {
        float2 p0 = upk(pv[d][0]), p1 = upk(pv[d][1]);
        float2 p2 = upk(pv[d][2]), p3 = upk(pv[d][3]);
        int gr = qbase + r0 + d;
        float4 o1 = {p0.x, p0.y, p1.x, p1.y};
        float4 o2 = {p2.x, p2.y, p3.x, p3.y};
        *reinterpret_cast<float4*>(&aout[gr * CC + c0])     = o1;
        *reinterpret_cast<float4*>(&aout[gr * CC + c0 + 4]) = o2;
    }
    if (tid < 128) g_l[blockIdx.y * NN + qbase + tid] = lrow[tid];
}

// ---------------- K3: combine halves -> h ----------------
__global__ __launch_bounds__(256) void combine_kernel()
{
    int i = blockIdx.x * 256 + threadIdx.x;
    int row = i >> 7;
    float l = g_l[row] + g_l[NN + row];
    g_h[i] = __fdividef(g_acc[i] + g_acc[NN * CC + i], l) + g_skip[i];
}

// ---------------- K4: row norms 0.5*|h|^2 ----------------
__global__ __launch_bounds__(256) void norm_kernel()
{
    int row  = blockIdx.x * 8 + (threadIdx.x >> 5);
    int lane = threadIdx.x & 31;
    const float* h = g_h + row * CC;
    float s = 0.f;
    for (int c = lane; c < CC; c += 32) { float v = h[c]; s += v * v; }
    s += __shfl_xor_sync(0xffffffffu, s, 16);
    s += __shfl_xor_sync(0xffffffffu, s, 8);
    s += __shfl_xor_sync(0xffffffffu, s, 4);
    s += __shfl_xor_sync(0xffffffffu, s, 2);
    s += __shfl_xor_sync(0xffffffffu, s, 1);
    if (lane == 0) g_norm[row] = 0.5f * s;
}

// ---------------- K5: kNN per key-half (top-7 of h_i.h_j - 0.5|h_j|^2) ----------------
__global__ __launch_bounds__(256, 1) void knn2_kernel()
{
    extern __shared__ float sm[];
    float* qsT = sm;
    float* kv  = qsT + 128 * S2;
    float* Ps  = kv  + 128 * S2;
    float* nr  = Ps  + 128 * S2;

    const int tid   = threadIdx.x;
    const int qbase = blockIdx.x * 128;
    const int kofs  = blockIdx.y * HALFN;

    const int ti = tid >> 4, tj = tid & 15;
    const int r0 = ti * 8,   c0 = tj * 8;

    for (int idx = tid; idx < 4096; idx += 256) {
        int r = idx & 127, c4 = (idx >> 7) << 2;
        float4 v = *reinterpret_cast<const float4*>(&g_h[(qbase + r) * CC + c4]);
        qsT[(c4 + 0) * S2 + r] = v.x;
        qsT[(c4 + 1) * S2 + r] = v.y;
        qsT[(c4 + 2) * S2 + r] = v.z;
        qsT[(c4 + 3) * S2 + r] = v.w;
    }

    float bestv[KNBR];
    int   besti[KNBR];
    #pragma unroll
    for (int t = 0; t < KNBR; t++) { bestv[t] = -1e30f; besti[t] = 0; }
    float vmin = -1e30f;

    for (int kb = 0; kb < HALFN; kb += 128) {
        __syncthreads();
        for (int idx = tid; idx < 4096; idx += 256) {
            int j = idx & 127, c4 = (idx >> 7) << 2;
            float4 v = *reinterpret_cast<const float4*>(&g_h[(kofs + kb + j) * CC + c4]);
            kv[(c4 + 0) * S2 + j] = v.x;
            kv[(c4 + 1) * S2 + j] = v.y;
            kv[(c4 + 2) * S2 + j] = v.z;
            kv[(c4 + 3) * S2 + j] = v.w;
        }
        if (tid < 128) nr[tid] = g_norm[kofs + kb + tid];
        __syncthreads();

        ull acc[8][4];
        #pragma unroll
        for (int d = 0; d < 8; d++)
            #pragma unroll
            for (int e = 0; e < 4; e++) acc[d][e] = 0ULL;

        #pragma unroll 4
        for (int k2 = 0; k2 < 128; k2++) {
            float4 qa  = *reinterpret_cast<const float4*>(&qsT[k2 * S2 + r0]);
            float4 qb4 = *reinterpret_cast<const float4*>(&qsT[k2 * S2 + r0 + 4]);
            ulonglong2 ka  = *reinterpret_cast<const ulonglong2*>(&kv[k2 * S2 + c0]);
            ulonglong2 kb2 = *reinterpret_cast<const ulonglong2*>(&kv[k2 * S2 + c0 + 4]);
            float qf[8] = {qa.x, qa.y, qa.z, qa.w, qb4.x, qb4.y, qb4.z, qb4.w};
            #pragma unroll
            for (int d = 0; d < 8; d++) {
                ull qd = dup2(qf[d]);
                acc[d][0] = ffma2(qd, ka.x,  acc[d][0]);
                acc[d][1] = ffma2(qd, ka.y,  acc[d][1]);
                acc[d][2] = ffma2(qd, kb2.x, acc[d][2]);
                acc[d][3] = ffma2(qd, kb2.y, acc[d][3]);
            }
        }

        #pragma unroll
        for (int d = 0; d < 8; d++) {
            int gr = qbase + r0 + d;
            float ev[8];
            #pragma unroll
            for (int e2 = 0; e2 < 4; e2++) {
                float2 s = upk(acc[d][e2]);
                int c = c0 + 2 * e2;
                int gc = kofs + kb + c;
                ev[2 * e2]     = (gr == gc)     ? -1e30f : (s.x - nr[c]);
                ev[2 * e2 + 1] = (gr == gc + 1) ? -1e30f : (s.y - nr[c + 1]);
            }
            float4 o1 = {ev[0], ev[1], ev[2], ev[3]};
            float4 o2 = {ev[4], ev[5], ev[6], ev[7]};
            *reinterpret_cast<float4*>(&Ps[(r0 + d) * S2 + c0])     = o1;
            *reinterpret_cast<float4*>(&Ps[(r0 + d) * S2 + c0 + 4]) = o2;
        }
        __syncthreads();

        if (tid < 128) {
            const float* pr = &Ps[tid * S2];
            for (int j = 0; j < 128; j++) {
                float v = pr[j];
                if (v > vmin) {
                    int p = KNBR - 1;
                    while (p > 0 && v > bestv[p - 1]) {
                        bestv[p] = bestv[p - 1];
                        besti[p] = besti[p - 1];
                        p--;
                    }
                    bestv[p] = v;
                    besti[p] = kofs + kb + j;
                    vmin = bestv[KNBR - 1];
                }
            }
        }
    }

    if (tid < 128) {
        int n = qbase + tid;
        #pragma unroll
        for (int t = 0; t < KNBR; t++) {
            g_cv[blockIdx.y * NN * KNBR + n * KNBR + t] = bestv[t];
            g_ci[blockIdx.y * NN * KNBR + n * KNBR + t] = besti[t];
        }
    }
}

// ---------------- K6: merge per-half top-7 lists ----------------
__global__ __launch_bounds__(256) void knn_merge_kernel()
{
    int n = blockIdx.x * 256 + threadIdx.x;
    const float* v0 = g_cv + n * KNBR;
    const int*   i0 = g_ci + n * KNBR;
    const float* v1 = g_cv + NN * KNBR + n * KNBR;
    const int*   i1 = g_ci + NN * KNBR + n * KNBR;
    int a = 0, b = 0;
    #pragma unroll
    for (int t = 0; t < KNBR; t++) {
        float va = v0[a], vb = v1[b];
        if (va >= vb) { g_idx[n * KNBR + t] = i0[a]; a++; }
        else          { g_idx[n * KNBR + t] = i1[b]; b++; }
    }
}

// ---------------- K7: m1 = h @ W1 (f32x2 packed) ----------------
__global__ __launch_bounds__(256) void gcn1_gemm(const float* __restrict__ W1)
{
    __shared__ float xs[32 * 129];
    const int tid = threadIdx.x;
    const int r0  = blockIdx.x * 32;

    for (int i = tid; i < 32 * CC; i += 256) {
        int r = i >> 7, c = i & 127;
        xs[r * 129 + c] = g_h[(r0 + r) * CC + c];
    }
    __syncthreads();

    const int ri = (tid >> 5) * 4;
    const int c0 = (tid & 31) * 4;

    ull acc[4][2];
    #pragma unroll
    for (int i = 0; i < 4; i++) { acc[i][0] = 0ULL; acc[i][1] = 0ULL; }

    #pragma unroll 4
    for (int k2 = 0; k2 < CC; k2++) {
        ulonglong2 wp = *reinterpret_cast<const ulonglong2*>(W1 + k2 * CC + c0);
        #pragma unroll
        for (int dr = 0; dr < 4; dr++) {
            ull x2 = dup2(xs[(ri + dr) * 129 + k2]);
            acc[dr][0] = ffma2(x2, wp.x, acc[dr][0]);
            acc[dr][1] = ffma2(x2, wp.y, acc[dr][1]);
        }
    }
    #pragma unroll
    for (int dr = 0; dr < 4; dr++) {
        float2 a0 = upk(acc[dr][0]), a1 = upk(acc[dr][1]);
        float4 o = {a0.x, a0.y, a1.x, a1.y};
        *reinterpret_cast<float4*>(g_m1 + (r0 + ri + dr) * CC + c0) = o;
    }
}

// ---------------- K8: GCN layer-1 gather + relu ----------------
__global__ __launch_bounds__(128) void gather1(const float* __restrict__ b1)
{
    int node = blockIdx.x;
    int c    = threadIdx.x;
    float s = g_m1[node * CC + c];
    #pragma unroll
    for (int t = 0; t < KNBR; t++) {
        int nb = g_idx[node * KNBR + t];
        s += g_m1[nb * CC + c];
    }
    g_h1[node * CC + c] = fmaxf(s * 0.125f + b1[c], 0.f);
}

// ---------------- K9: m2 = h1 @ W2 (OUT_C = 1) ----------------
__global__ __launch_bounds__(256) void m2_kernel(const float* __restrict__ W2)
{
    int row  = blockIdx.x * 8 + (threadIdx.x >> 5);
    int lane = threadIdx.x & 31;
    float s = 0.f;
    for (int c = lane; c < CC; c += 32) s += g_h1[row * CC + c] * W2[c];
    s += __shfl_xor_sync(0xffffffffu, s, 16);
    s += __shfl_xor_sync(0xffffffffu, s, 8);
    s += __shfl_xor_sync(0xffffffffu, s, 4);
    s += __shfl_xor_sync(0xffffffffu, s, 2);
    s += __shfl_xor_sync(0xffffffffu, s, 1);
    if (lane == 0) g_m2[row] = s;
}

// ---------------- K10: GCN layer-2 gather -> output ----------------
__global__ __launch_bounds__(256) void out_kernel(const float* __restrict__ b2,
                                                  float* __restrict__ out)
{
    int n = blockIdx.x * 256 + threadIdx.x;
    float s = g_m2[n];
    #pragma unroll
    for (int t = 0; t < KNBR; t++) s += g_m2[g_idx[n * KNBR + t]];
    out[n] = s * 0.125f + b2[0];
}

// ---------------- launch ----------------
extern "C" void kernel_launch(void* const* d_in, const int* in_sizes, int n_in,
                              void* d_out, int out_size)
{
    const float* x   = (const float*)d_in[0];
    const float* Wq  = (const float*)d_in[1];
    const float* bq  = (const float*)d_in[2];
    const float* Wk  = (const float*)d_in[3];
    const float* bk  = (const float*)d_in[4];
    const float* Wv  = (const float*)d_in[5];
    const float* bv  = (const float*)d_in[6];
    const float* Wsk = (const float*)d_in[7];
    const float* bsk = (const float*)d_in[8];
    const float* W1  = (const float*)d_in[9];
    const float* b1  = (const float*)d_in[10];
    const float* W2  = (const float*)d_in[11];
    const float* b2  = (const float*)d_in[12];
    float* out = (float*)d_out;

    const int big_smem = BIG_SMEM_FLOATS * (int)sizeof(float);  // 203264 B
    cudaFuncSetAttribute(attn2_kernel, cudaFuncAttributeMaxDynamicSharedMemorySize, big_smem);
    cudaFuncSetAttribute(knn2_kernel,  cudaFuncAttributeMaxDynamicSharedMemorySize, big_smem);

    proj_kernel<<<NN / 32, 256>>>(x, Wq, bq, Wk, bk, Wv, bv, Wsk, bsk);
    attn2_kernel<<<dim3(NN / 128, 2), 256, big_smem>>>();
    combine_kernel<<<NN * CC / 256, 256>>>();
    norm_kernel<<<NN / 8, 256>>>();
    knn2_kernel<<<dim3(NN / 128, 2), 256, big_smem>>>();
    knn_merge_kernel<<<NN / 256, 256>>>();
    gcn1_gemm<<<NN / 32, 256>>>(W1);
    gather1<<<NN, CC>>>(b1);
    m2_kernel<<<NN / 8, 256>>>(W2);
    out_kernel<<<NN / 256, 256>>>(b2, out);
}

// round 4
// speedup vs baseline: 2.8088x; 1.8771x over previous
#include <cuda_runtime.h>
#include <cuda_bf16.h>
#include <cstdint>

#define NN    8192
#define CC    128
#define KNBR  7
#define HALFN 4096
#define NCAND 16

typedef unsigned long long ull;

// ---------------- device scratch ----------------
__device__ float g_skip[NN * CC];
__device__ float g_h[NN * CC];
__device__ float g_acc[2 * NN * CC];
__device__ float g_l[2 * NN];
__device__ float g_norm[NN];
__device__ float g_cv16[2 * NN * NCAND];
__device__ int   g_ci16[2 * NN * NCAND];
__device__ int   g_idx[NN * KNBR];
__device__ float g_m1[NN * CC];
__device__ float g_h1[NN * CC];
__device__ float g_m2[NN];
__device__ __nv_bfloat16 g_qb0[NN * CC], g_qb1[NN * CC];
__device__ __nv_bfloat16 g_kb0[NN * CC], g_kb1[NN * CC];
__device__ __nv_bfloat16 g_vb0[NN * CC], g_vb1[NN * CC];
__device__ __nv_bfloat16 g_hb0[NN * CC], g_hb1[NN * CC];

// ---------------- packed fp32x2 (for proj/gcn SIMT GEMMs) ----------------
__device__ __forceinline__ ull ffma2(ull a, ull b, ull c) {
    ull d;
    asm("fma.rn.f32x2 %0, %1, %2, %3;" : "=l"(d) : "l"(a), "l"(b), "l"(c));
    return d;
}
__device__ __forceinline__ ull dup2(float x) {
    ull d;
    asm("mov.b64 %0, {%1, %1};" : "=l"(d) : "f"(x));
    return d;
}
__device__ __forceinline__ float2 upk(ull v) {
    float2 r;
    asm("mov.b64 {%0, %1}, %2;" : "=f"(r.x), "=f"(r.y) : "l"(v));
    return r;
}

// ---------------- mma/ldmatrix helpers (portable sm_80+ path) ----------------
__device__ __forceinline__ uint32_t smem_u32(const void* p) {
    uint32_t a;
    asm("{ .reg .u64 t; cvta.to.shared.u64 t, %1; cvt.u32.u64 %0, t; }" : "=r"(a) : "l"(p));
    return a;
}
__device__ __forceinline__ void ldsm4(uint32_t* r, uint32_t a) {
    asm volatile("ldmatrix.sync.aligned.m8n8.x4.shared.b16 {%0,%1,%2,%3}, [%4];"
                 : "=r"(r[0]), "=r"(r[1]), "=r"(r[2]), "=r"(r[3]) : "r"(a));
}
__device__ __forceinline__ void ldsm4t(uint32_t* r, uint32_t a) {
    asm volatile("ldmatrix.sync.aligned.m8n8.x4.trans.shared.b16 {%0,%1,%2,%3}, [%4];"
                 : "=r"(r[0]), "=r"(r[1]), "=r"(r[2]), "=r"(r[3]) : "r"(a));
}
__device__ __forceinline__ void mma16816(float* c, const uint32_t* a, uint32_t b0, uint32_t b1) {
    asm volatile(
        "mma.sync.aligned.m16n8k16.row.col.f32.bf16.bf16.f32 "
        "{%0,%1,%2,%3}, {%4,%5,%6,%7}, {%8,%9}, {%0,%1,%2,%3};"
        : "+f"(c[0]), "+f"(c[1]), "+f"(c[2]), "+f"(c[3])
        : "r"(a[0]), "r"(a[1]), "r"(a[2]), "r"(a[3]), "r"(b0), "r"(b1));
}
__device__ __forceinline__ uint32_t pack_bf(float x, float y) {
    __nv_bfloat162 t = __floats2bfloat162_rn(x, y);
    return *reinterpret_cast<uint32_t*>(&t);
}
__device__ __forceinline__ void split_pair(float x, float y, uint32_t& p0, uint32_t& p1) {
    __nv_bfloat16 bx = __float2bfloat16_rn(x), by = __float2bfloat16_rn(y);
    __nv_bfloat162 t; t.x = bx; t.y = by;
    p0 = *reinterpret_cast<uint32_t*>(&t);
    p1 = pack_bf(x - __bfloat162float(bx), y - __bfloat162float(by));
}
// load 128x128 bf16 tile into smem with row stride 136 halves (272B)
__device__ __forceinline__ void ld_tile(char* dst, const __nv_bfloat16* __restrict__ src, int tid) {
    #pragma unroll
    for (int i = 0; i < 8; i++) {
        int idx = tid + i * 256;
        int row = idx >> 4, ch = idx & 15;
        uint4 v = *reinterpret_cast<const uint4*>(src + row * CC + ch * 8);
        *reinterpret_cast<uint4*>(dst + row * 272 + ch * 16) = v;
    }
}

// ---------------- K1: fused projections -> bf16 splits + skip ----------------
__global__ __launch_bounds__(256) void proj_kernel(
    const float* __restrict__ x,
    const float* __restrict__ Wq, const float* __restrict__ bq,
    const float* __restrict__ Wk, const float* __restrict__ bk,
    const float* __restrict__ Wv, const float* __restrict__ bv,
    const float* __restrict__ Ws, const float* __restrict__ bs)
{
    __shared__ float xs[32 * 129];
    const int tid = threadIdx.x;
    const int r0  = blockIdx.x * 32;
    const float SCALE = 0.08838834764831843f;  // 1/sqrt(128)

    for (int i = tid; i < 32 * CC; i += 256) {
        int r = i >> 7, c = i & 127;
        xs[r * 129 + c] = x[(r0 + r) * CC + c];
    }
    __syncthreads();

    const int ri = (tid >> 5) * 4;
    const int c0 = (tid & 31) * 4;

    const float* Wt[4] = {Wq, Wk, Wv, Ws};
    const float* bt[4] = {bq, bk, bv, bs};

    #pragma unroll
    for (int w = 0; w < 4; w++) {
        const float* W = Wt[w];
        ull acc[4][2];
        #pragma unroll
        for (int i = 0; i < 4; i++) { acc[i][0] = 0ULL; acc[i][1] = 0ULL; }

        #pragma unroll 4
        for (int k2 = 0; k2 < CC; k2++) {
            ulonglong2 wp = *reinterpret_cast<const ulonglong2*>(W + k2 * CC + c0);
            #pragma unroll
            for (int dr = 0; dr < 4; dr++) {
                ull x2 = dup2(xs[(ri + dr) * 129 + k2]);
                acc[dr][0] = ffma2(x2, wp.x, acc[dr][0]);
                acc[dr][1] = ffma2(x2, wp.y, acc[dr][1]);
            }
        }
        float4 bb = *reinterpret_cast<const float4*>(bt[w] + c0);
        #pragma unroll
        for (int dr = 0; dr < 4; dr++) {
            float2 a0 = upk(acc[dr][0]), a1 = upk(acc[dr][1]);
            int row = r0 + ri + dr;
            float ox = a0.x + bb.x, oy = a0.y + bb.y;
            float oz = a1.x + bb.z, ow = a1.y + bb.w;
            if (w == 3) {
                float4 o = {ox, oy, oz, ow};
                *reinterpret_cast<float4*>(g_skip + row * CC + c0) = o;
            } else {
                float s = (w == 0) ? SCALE : 1.f;
                ox *= s; oy *= s; oz *= s; ow *= s;
                uint32_t lo0, hi0, lo1, hi1;
                split_pair(ox, oy, lo0, hi0);
                split_pair(oz, ow, lo1, hi1);
                __nv_bfloat16* d0 = (w == 0) ? g_qb0 : (w == 1) ? g_kb0 : g_vb0;
                __nv_bfloat16* d1 = (w == 0) ? g_qb1 : (w == 1) ? g_kb1 : g_vb1;
                uint2 u0 = {lo0, lo1};
                uint2 u1 = {hi0, hi1};
                *reinterpret_cast<uint2*>(d0 + row * CC + c0) = u0;
                *reinterpret_cast<uint2*>(d1 + row * CC + c0) = u1;
            }
        }
    }
}

// ---------------- K2: flash attention via mma.sync (bf16 2-split) ----------------
#define AQ0 0
#define AQ1 34816
#define AK0 69632
#define AK1 104448
#define AV0 139264
#define AV1 174080
#define ATTN_SMEM 208896

__global__ __launch_bounds__(256, 1) void attn_mma_kernel()
{
    extern __shared__ __align__(16) char smc[];
    const uint32_t sb = smem_u32(smc);
    const int tid  = threadIdx.x, wid = tid >> 5, lane = tid & 31;
    const int qbase = blockIdx.x * 128;
    const int kofs  = blockIdx.y * HALFN;

    ld_tile(smc + AQ0, g_qb0 + (size_t)qbase * CC, tid);
    ld_tile(smc + AQ1, g_qb1 + (size_t)qbase * CC, tid);

    const int r0   = wid * 16;
    const int qrow = lane >> 2, qc = (lane & 3) * 2;
    const int gr0  = qbase + r0 + qrow, gr1 = gr0 + 8;

    const uint32_t aoff = (uint32_t)((r0 + (lane & 15)) * 272 + ((lane >> 4) & 1) * 16);
    const uint32_t boff = (uint32_t)(((lane & 7) + ((lane >> 4) & 1) * 8) * 272 + ((lane >> 3) & 1) * 16);
    const uint32_t voff = (uint32_t)(((lane & 7) + ((lane >> 3) & 1) * 8) * 272 + ((lane >> 4) & 1) * 16);

    float pv[16][4];
    #pragma unroll
    for (int i = 0; i < 16; i++)
        #pragma unroll
        for (int j = 0; j < 4; j++) pv[i][j] = 0.f;
    float l0 = 0.f, l1 = 0.f;

    for (int kb = 0; kb < HALFN; kb += 128) {
        __syncthreads();
        ld_tile(smc + AK0, g_kb0 + (size_t)(kofs + kb) * CC, tid);
        ld_tile(smc + AK1, g_kb1 + (size_t)(kofs + kb) * CC, tid);
        ld_tile(smc + AV0, g_vb0 + (size_t)(kofs + kb) * CC, tid);
        ld_tile(smc + AV1, g_vb1 + (size_t)(kofs + kb) * CC, tid);
        __syncthreads();

        float sc[16][4];
        #pragma unroll
        for (int i = 0; i < 16; i++)
            #pragma unroll
            for (int j = 0; j < 4; j++) sc[i][j] = 0.f;

        // scores: q0k0 + q0k1 + q1k0
        #pragma unroll
        for (int p = 0; p < 3; p++) {
            uint32_t qb2 = sb + ((p == 2) ? AQ1 : AQ0);
            uint32_t kb2 = sb + ((p == 1) ? AK1 : AK0);
            #pragma unroll
            for (int kc = 0; kc < 8; kc++) {
                uint32_t a[4];
                ldsm4(a, qb2 + aoff + kc * 32);
                #pragma unroll
                for (int nt2 = 0; nt2 < 8; nt2++) {
                    uint32_t b[4];
                    ldsm4(b, kb2 + (uint32_t)(nt2 * 16 * 272) + boff + kc * 32);
                    mma16816(sc[2 * nt2],     a, b[0], b[1]);
                    mma16816(sc[2 * nt2 + 1], a, b[2], b[3]);
                }
            }
        }

        // exp (no max; scores bounded), diag mask, row sums
        float rs0 = 0.f, rs1 = 0.f;
        #pragma unroll
        for (int nt = 0; nt < 16; nt++) {
            int gc = kofs + kb + nt * 8 + qc;
            float e0 = (gr0 == gc)     ? 0.f : __expf(sc[nt][0]);
            float e1 = (gr0 == gc + 1) ? 0.f : __expf(sc[nt][1]);
            float e2 = (gr1 == gc)     ? 0.f : __expf(sc[nt][2]);
            float e3 = (gr1 == gc + 1) ? 0.f : __expf(sc[nt][3]);
            sc[nt][0] = e0; sc[nt][1] = e1; sc[nt][2] = e2; sc[nt][3] = e3;
            rs0 += e0 + e1; rs1 += e2 + e3;
        }
        rs0 += __shfl_xor_sync(0xffffffffu, rs0, 1);
        rs0 += __shfl_xor_sync(0xffffffffu, rs0, 2);
        rs1 += __shfl_xor_sync(0xffffffffu, rs1, 1);
        rs1 += __shfl_xor_sync(0xffffffffu, rs1, 2);
        l0 += rs0; l1 += rs1;

        // PV: p0v0 + p0v1 + p1v0
        #pragma unroll
        for (int kc = 0; kc < 8; kc++) {
            uint32_t p0[4], p1[4];
            split_pair(sc[2 * kc][0],     sc[2 * kc][1],     p0[0], p1[0]);
            split_pair(sc[2 * kc][2],     sc[2 * kc][3],     p0[1], p1[1]);
            split_pair(sc[2 * kc + 1][0], sc[2 * kc + 1][1], p0[2], p1[2]);
            split_pair(sc[2 * kc + 1][2], sc[2 * kc + 1][3], p0[3], p1[3]);
            #pragma unroll
            for (int nt2 = 0; nt2 < 8; nt2++) {
                uint32_t v0f[4], v1f[4];
                ldsm4t(v0f, sb + AV0 + (uint32_t)(kc * 16 * 272) + voff + nt2 * 32);
                ldsm4t(v1f, sb + AV1 + (uint32_t)(kc * 16 * 272) + voff + nt2 * 32);
                mma16816(pv[2 * nt2],     p0, v0f[0], v0f[1]);
                mma16816(pv[2 * nt2],     p0, v1f[0], v1f[1]);
                mma16816(pv[2 * nt2],     p1, v0f[0], v0f[1]);
                mma16816(pv[2 * nt2 + 1], p0, v0f[2], v0f[3]);
                mma16816(pv[2 * nt2 + 1], p0, v1f[2], v1f[3]);
                mma16816(pv[2 * nt2 + 1], p1, v0f[2], v0f[3]);
            }
        }
    }

    float* aout = g_acc + (size_t)blockIdx.y * NN * CC;
    #pragma unroll
    for (int nt = 0; nt < 16; nt++) {
        int c = nt * 8 + qc;
        *reinterpret_cast<float2*>(aout + (size_t)gr0 * CC + c) = make_float2(pv[nt][0], pv[nt][1]);
        *reinterpret_cast<float2*>(aout + (size_t)gr1 * CC + c) = make_float2(pv[nt][2], pv[nt][3]);
    }
    if ((lane & 3) == 0) {
        g_l[blockIdx.y * NN + gr0] = l0;
        g_l[blockIdx.y * NN + gr1] = l1;
    }
}

// ---------------- K3: combine halves -> h ----------------
__global__ __launch_bounds__(256) void combine_kernel()
{
    int i = blockIdx.x * 256 + threadIdx.x;
    int row = i >> 7;
    float l = g_l[row] + g_l[NN + row];
    g_h[i] = __fdividef(g_acc[i] + g_acc[NN * CC + i], l) + g_skip[i];
}

// ---------------- K4: row norms + bf16 2-way split of h ----------------
__global__ __launch_bounds__(256) void norm_split_kernel()
{
    int row  = blockIdx.x * 8 + (threadIdx.x >> 5);
    int lane = threadIdx.x & 31;
    const float* h = g_h + row * CC;
    float s = 0.f;
    for (int c = lane; c < CC; c += 32) {
        float v = h[c];
        s += v * v;
        __nv_bfloat16 b0 = __float2bfloat16_rn(v);
        g_hb0[row * CC + c] = b0;
        g_hb1[row * CC + c] = __float2bfloat16_rn(v - __bfloat162float(b0));
    }
    s += __shfl_xor_sync(0xffffffffu, s, 16);
    s += __shfl_xor_sync(0xffffffffu, s, 8);
    s += __shfl_xor_sync(0xffffffffu, s, 4);
    s += __shfl_xor_sync(0xffffffffu, s, 2);
    s += __shfl_xor_sync(0xffffffffu, s, 1);
    if (lane == 0) g_norm[row] = 0.5f * s;
}

// ---------------- K5: kNN candidates via mma.sync ----------------
#define KQ0 0
#define KQ1 34816
#define KK0 69632
#define KK1 104448
#define KPS 139264               // 128 x 129 f32 = 66048 B
#define KNR 205312               // 128 f32
#define KNN_SMEM 205824

__global__ __launch_bounds__(256, 1) void knn_mma_kernel()
{
    extern __shared__ __align__(16) char smc[];
    const uint32_t sb = smem_u32(smc);
    float* Ps   = reinterpret_cast<float*>(smc + KPS);
    float* nr_s = reinterpret_cast<float*>(smc + KNR);

    const int tid  = threadIdx.x, wid = tid >> 5, lane = tid & 31;
    const int qbase = blockIdx.x * 128;
    const int kofs  = blockIdx.y * HALFN;

    ld_tile(smc + KQ0, g_hb0 + (size_t)qbase * CC, tid);
    ld_tile(smc + KQ1, g_hb1 + (size_t)qbase * CC, tid);

    const int r0   = wid * 16;
    const int qrow = lane >> 2, qc = (lane & 3) * 2;
    const int gr0  = qbase + r0 + qrow, gr1 = gr0 + 8;
    const int lr0  = r0 + qrow, lr1 = lr0 + 8;

    const uint32_t aoff = (uint32_t)((r0 + (lane & 15)) * 272 + ((lane >> 4) & 1) * 16);
    const uint32_t boff = (uint32_t)(((lane & 7) + ((lane >> 4) & 1) * 8) * 272 + ((lane >> 3) & 1) * 16);

    // scan state: this thread scans row (tid>>1), col half (tid&1)
    const int srow  = tid >> 1;
    const int scol0 = (tid & 1) * 64;
    float tv[NCAND]; int ti[NCAND];
    #pragma unroll
    for (int t = 0; t < NCAND; t++) { tv[t] = -3e38f; ti[t] = 0; }
    float vmin = -3e38f;

    for (int kb = 0; kb < HALFN; kb += 128) {
        __syncthreads();
        ld_tile(smc + KK0, g_hb0 + (size_t)(kofs + kb) * CC, tid);
        ld_tile(smc + KK1, g_hb1 + (size_t)(kofs + kb) * CC, tid);
        if (tid < 128) nr_s[tid] = g_norm[kofs + kb + tid];
        __syncthreads();

        float sc[16][4];
        #pragma unroll
        for (int i = 0; i < 16; i++)
            #pragma unroll
            for (int j = 0; j < 4; j++) sc[i][j] = 0.f;

        #pragma unroll
        for (int p = 0; p < 3; p++) {
            uint32_t qb2 = sb + ((p == 2) ? KQ1 : KQ0);
            uint32_t kb2 = sb + ((p == 1) ? KK1 : KK0);
            #pragma unroll
            for (int kc = 0; kc < 8; kc++) {
                uint32_t a[4];
                ldsm4(a, qb2 + aoff + kc * 32);
                #pragma unroll
                for (int nt2 = 0; nt2 < 8; nt2++) {
                    uint32_t b[4];
                    ldsm4(b, kb2 + (uint32_t)(nt2 * 16 * 272) + boff + kc * 32);
                    mma16816(sc[2 * nt2],     a, b[0], b[1]);
                    mma16816(sc[2 * nt2 + 1], a, b[2], b[3]);
                }
            }
        }

        // adjust by -0.5|h_j|^2, mask diag, write to Ps
        #pragma unroll
        for (int nt = 0; nt < 16; nt++) {
            int c = nt * 8 + qc;
            int gc = kofs + kb + c;
            float v0 = sc[nt][0] - nr_s[c];
            float v1 = sc[nt][1] - nr_s[c + 1];
            float v2 = sc[nt][2] - nr_s[c];
            float v3 = sc[nt][3] - nr_s[c + 1];
            if (gr0 == gc)     v0 = -3e38f;
            if (gr0 == gc + 1) v1 = -3e38f;
            if (gr1 == gc)     v2 = -3e38f;
            if (gr1 == gc + 1) v3 = -3e38f;
            Ps[lr0 * 129 + c]     = v0;
            Ps[lr0 * 129 + c + 1] = v1;
            Ps[lr1 * 129 + c]     = v2;
            Ps[lr1 * 129 + c + 1] = v3;
        }
        __syncthreads();

        // scan 64 cols of one row, keep top-16
        const float* pr = Ps + srow * 129 + scol0;
        const int gbase = kofs + kb + scol0;
        #pragma unroll 4
        for (int j = 0; j < 64; j++) {
            float v = pr[j];
            if (v > vmin) {
                float cv = v; int cidx = gbase + j;
                #pragma unroll
                for (int t = 0; t < NCAND; t++) {
                    if (cv > tv[t]) {
                        float tmp = tv[t]; tv[t] = cv; cv = tmp;
                        int tj = ti[t]; ti[t] = cidx; cidx = tj;
                    }
                }
                vmin = tv[NCAND - 1];
            }
        }
        __syncthreads();   // before Ps rewrite next tile
    }

    // dump per-scanner lists, then merge pairs -> top-16 per row
    float* mv = Ps;                                    // [256][16]
    int*   mi = reinterpret_cast<int*>(Ps + 256 * NCAND);
    #pragma unroll
    for (int t = 0; t < NCAND; t++) {
        mv[tid * NCAND + t] = tv[t];
        mi[tid * NCAND + t] = ti[t];
    }
    __syncthreads();
    if (tid < 128) {
        const float* va = mv + (2 * tid) * NCAND;
        const int*   ia = mi + (2 * tid) * NCAND;
        const float* vb = mv + (2 * tid + 1) * NCAND;
        const int*   ib = mi + (2 * tid + 1) * NCAND;
        float* outv = g_cv16 + (size_t)blockIdx.y * NN * NCAND + (size_t)(qbase + tid) * NCAND;
        int*   outi = g_ci16 + (size_t)blockIdx.y * NN * NCAND + (size_t)(qbase + tid) * NCAND;
        int a = 0, b = 0;
        #pragma unroll
        for (int t = 0; t < NCAND; t++) {
            float xa = va[a], xb = vb[b];
            bool ta = (xa > xb) || (xa == xb && ia[a] < ib[b]);
            if (ta) { outv[t] = xa; outi[t] = ia[a]; a++; }
            else    { outv[t] = xb; outi[t] = ib[b]; b++; }
        }
    }
}

// ---------------- K6: exact rescore of 32 candidates -> top-7 ----------------
__global__ __launch_bounds__(256) void knn_rescore_kernel()
{
    int node = (blockIdx.x * 256 + threadIdx.x) >> 5;
    int lane = threadIdx.x & 31;

    float4 hv = *reinterpret_cast<const float4*>(g_h + (size_t)node * CC + lane * 4);
    int half = lane >> 4, slot = lane & 15;
    int ci = g_ci16[(size_t)half * NN * NCAND + (size_t)node * NCAND + slot];

    float myv = -3e38f;
    for (int c = 0; c < 32; c++) {
        int cj = __shfl_sync(0xffffffffu, ci, c);
        float4 hc = *reinterpret_cast<const float4*>(g_h + (size_t)cj * CC + lane * 4);
        float p = hv.x * hc.x + hv.y * hc.y + hv.z * hc.z + hv.w * hc.w;
        #pragma unroll
        for (int m = 16; m >= 1; m >>= 1) p += __shfl_xor_sync(0xffffffffu, p, m);
        if (lane == c) myv = p - g_norm[cj];
    }

    float v = myv; int idx = ci;
    #pragma unroll
    for (int t = 0; t < KNBR; t++) {
        float bv = v; int bidx = idx;
        #pragma unroll
        for (int m = 16; m >= 1; m >>= 1) {
            float ov = __shfl_xor_sync(0xffffffffu, bv, m);
            int   oi = __shfl_xor_sync(0xffffffffu, bidx, m);
            if (ov > bv || (ov == bv && oi < bidx)) { bv = ov; bidx = oi; }
        }
        if (lane == 0) g_idx[node * KNBR + t] = bidx;
        if (idx == bidx) v = -3.3e38f;
    }
}

// ---------------- K7: m1 = h @ W1 ----------------
__global__ __launch_bounds__(256) void gcn1_gemm(const float* __restrict__ W1)
{
    __shared__ float xs[32 * 129];
    const int tid = threadIdx.x;
    const int r0  = blockIdx.x * 32;

    for (int i = tid; i < 32 * CC; i += 256) {
        int r = i >> 7, c = i & 127;
        xs[r * 129 + c] = g_h[(r0 + r) * CC + c];
    }
    __syncthreads();

    const int ri = (tid >> 5) * 4;
    const int c0 = (tid & 31) * 4;

    ull acc[4][2];
    #pragma unroll
    for (int i = 0; i < 4; i++) { acc[i][0] = 0ULL; acc[i][1] = 0ULL; }

    #pragma unroll 4
    for (int k2 = 0; k2 < CC; k2++) {
        ulonglong2 wp = *reinterpret_cast<const ulonglong2*>(W1 + k2 * CC + c0);
        #pragma unroll
        for (int dr = 0; dr < 4; dr++) {
            ull x2 = dup2(xs[(ri + dr) * 129 + k2]);
            acc[dr][0] = ffma2(x2, wp.x, acc[dr][0]);
            acc[dr][1] = ffma2(x2, wp.y, acc[dr][1]);
        }
    }
    #pragma unroll
    for (int dr = 0; dr < 4; dr++) {
        float2 a0 = upk(acc[dr][0]), a1 = upk(acc[dr][1]);
        float4 o = {a0.x, a0.y, a1.x, a1.y};
        *reinterpret_cast<float4*>(g_m1 + (r0 + ri + dr) * CC + c0) = o;
    }
}

// ---------------- K8: GCN layer-1 gather + relu ----------------
__global__ __launch_bounds__(128) void gather1(const float* __restrict__ b1)
{
    int node = blockIdx.x;
    int c    = threadIdx.x;
    float s = g_m1[node * CC + c];
    #pragma unroll
    for (int t = 0; t < KNBR; t++) {
        int nb = g_idx[node * KNBR + t];
        s += g_m1[nb * CC + c];
    }
    g_h1[node * CC + c] = fmaxf(s * 0.125f + b1[c], 0.f);
}

// ---------------- K9: m2 = h1 @ W2 ----------------
__global__ __launch_bounds__(256) void m2_kernel(const float* __restrict__ W2)
{
    int row  = blockIdx.x * 8 + (threadIdx.x >> 5);
    int lane = threadIdx.x & 31;
    float s = 0.f;
    for (int c = lane; c < CC; c += 32) s += g_h1[row * CC + c] * W2[c];
    s += __shfl_xor_sync(0xffffffffu, s, 16);
    s += __shfl_xor_sync(0xffffffffu, s, 8);
    s += __shfl_xor_sync(0xffffffffu, s, 4);
    s += __shfl_xor_sync(0xffffffffu, s, 2);
    s += __shfl_xor_sync(0xffffffffu, s, 1);
    if (lane == 0) g_m2[row] = s;
}

// ---------------- K10: GCN layer-2 gather -> output ----------------
__global__ __launch_bounds__(256) void out_kernel(const float* __restrict__ b2,
                                                  float* __restrict__ out)
{
    int n = blockIdx.x * 256 + threadIdx.x;
    float s = g_m2[n];
    #pragma unroll
    for (int t = 0; t < KNBR; t++) s += g_m2[g_idx[n * KNBR + t]];
    out[n] = s * 0.125f + b2[0];
}

// ---------------- launch ----------------
extern "C" void kernel_launch(void* const* d_in, const int* in_sizes, int n_in,
                              void* d_out, int out_size)
{
    const float* x   = (const float*)d_in[0];
    const float* Wq  = (const float*)d_in[1];
    const float* bq  = (const float*)d_in[2];
    const float* Wk  = (const float*)d_in[3];
    const float* bk  = (const float*)d_in[4];
    const float* Wv  = (const float*)d_in[5];
    const float* bv  = (const float*)d_in[6];
    const float* Wsk = (const float*)d_in[7];
    const float* bsk = (const float*)d_in[8];
    const float* W1  = (const float*)d_in[9];
    const float* b1  = (const float*)d_in[10];
    const float* W2  = (const float*)d_in[11];
    const float* b2  = (const float*)d_in[12];
    float* out = (float*)d_out;

    cudaFuncSetAttribute(attn_mma_kernel, cudaFuncAttributeMaxDynamicSharedMemorySize, ATTN_SMEM);
    cudaFuncSetAttribute(knn_mma_kernel,  cudaFuncAttributeMaxDynamicSharedMemorySize, KNN_SMEM);

    proj_kernel<<<NN / 32, 256>>>(x, Wq, bq, Wk, bk, Wv, bv, Wsk, bsk);
    attn_mma_kernel<<<dim3(NN / 128, 2), 256, ATTN_SMEM>>>();
    combine_kernel<<<NN * CC / 256, 256>>>();
    norm_split_kernel<<<NN / 8, 256>>>();
    knn_mma_kernel<<<dim3(NN / 128, 2), 256, KNN_SMEM>>>();
    knn_rescore_kernel<<<NN / 8, 256>>>();
    gcn1_gemm<<<NN / 32, 256>>>(W1);
    gather1<<<NN, CC>>>(b1);
    m2_kernel<<<NN / 8, 256>>>(W2);
    out_kernel<<<NN / 256, 256>>>(b2, out);
}

// round 5
// speedup vs baseline: 3.7435x; 1.3328x over previous
#include <cuda_runtime.h>
#include <cuda_bf16.h>
#include <cstdint>

#define NN    8192
#define CC    128
#define KNBR  7
#define HALFN 4096
#define NCAND 16

typedef unsigned long long ull;

// ---------------- device scratch ----------------
__device__ float g_skip[NN * CC];
__device__ float g_h[NN * CC];
__device__ float g_acc[2 * NN * CC];
__device__ float g_l[2 * NN];
__device__ float g_norm[NN];
__device__ float g_cv16[2 * NN * NCAND];
__device__ int   g_ci16[2 * NN * NCAND];
__device__ int   g_idx[NN * KNBR];
__device__ float g_m1[NN * CC];
__device__ float g_h1[NN * CC];
__device__ float g_m2[NN];
__device__ __nv_bfloat16 g_qb0[NN * CC], g_qb1[NN * CC];
__device__ __nv_bfloat16 g_kb0[NN * CC], g_kb1[NN * CC];
__device__ __nv_bfloat16 g_vb0[NN * CC], g_vb1[NN * CC];
__device__ __nv_bfloat16 g_hb0[NN * CC];

// ---------------- packed fp32x2 (SIMT GEMMs) ----------------
__device__ __forceinline__ ull ffma2(ull a, ull b, ull c) {
    ull d;
    asm("fma.rn.f32x2 %0, %1, %2, %3;" : "=l"(d) : "l"(a), "l"(b), "l"(c));
    return d;
}
__device__ __forceinline__ ull dup2(float x) {
    ull d;
    asm("mov.b64 %0, {%1, %1};" : "=l"(d) : "f"(x));
    return d;
}
__device__ __forceinline__ float2 upk(ull v) {
    float2 r;
    asm("mov.b64 {%0, %1}, %2;" : "=f"(r.x), "=f"(r.y) : "l"(v));
    return r;
}

// ---------------- mma / ldmatrix / cp.async helpers ----------------
__device__ __forceinline__ uint32_t smem_u32(const void* p) {
    uint32_t a;
    asm("{ .reg .u64 t; cvta.to.shared.u64 t, %1; cvt.u32.u64 %0, t; }" : "=r"(a) : "l"(p));
    return a;
}
__device__ __forceinline__ void ldsm4(uint32_t* r, uint32_t a) {
    asm volatile("ldmatrix.sync.aligned.m8n8.x4.shared.b16 {%0,%1,%2,%3}, [%4];"
                 : "=r"(r[0]), "=r"(r[1]), "=r"(r[2]), "=r"(r[3]) : "r"(a));
}
__device__ __forceinline__ void ldsm4t(uint32_t* r, uint32_t a) {
    asm volatile("ldmatrix.sync.aligned.m8n8.x4.trans.shared.b16 {%0,%1,%2,%3}, [%4];"
                 : "=r"(r[0]), "=r"(r[1]), "=r"(r[2]), "=r"(r[3]) : "r"(a));
}
__device__ __forceinline__ void mma16816(float* c, const uint32_t* a, uint32_t b0, uint32_t b1) {
    asm volatile(
        "mma.sync.aligned.m16n8k16.row.col.f32.bf16.bf16.f32 "
        "{%0,%1,%2,%3}, {%4,%5,%6,%7}, {%8,%9}, {%0,%1,%2,%3};"
        : "+f"(c[0]), "+f"(c[1]), "+f"(c[2]), "+f"(c[3])
        : "r"(a[0]), "r"(a[1]), "r"(a[2]), "r"(a[3]), "r"(b0), "r"(b1));
}
#define CP_COMMIT() asm volatile("cp.async.commit_group;" ::: "memory")
#define CP_WAIT(n)  asm volatile("cp.async.wait_group %0;" :: "n"(n) : "memory")

__device__ __forceinline__ uint32_t pack_bf(float x, float y) {
    __nv_bfloat162 t = __floats2bfloat162_rn(x, y);
    return *reinterpret_cast<uint32_t*>(&t);
}
__device__ __forceinline__ void split_pair(float x, float y, uint32_t& p0, uint32_t& p1) {
    __nv_bfloat16 bx = __float2bfloat16_rn(x), by = __float2bfloat16_rn(y);
    __nv_bfloat162 t; t.x = bx; t.y = by;
    p0 = *reinterpret_cast<uint32_t*>(&t);
    p1 = pack_bf(x - __bfloat162float(bx), y - __bfloat162float(by));
}
// async 128x128 bf16 tile -> smem rows of 272B
__device__ __forceinline__ void ld_tile_async(uint32_t dst, const __nv_bfloat16* __restrict__ src, int tid) {
    #pragma unroll
    for (int i = 0; i < 8; i++) {
        int idx = tid + i * 256;
        int row = idx >> 4, ch = idx & 15;
        asm volatile("cp.async.cg.shared.global [%0], [%1], 16;" ::
            "r"(dst + (uint32_t)(row * 272 + ch * 16)), "l"(src + row * CC + ch * 8) : "memory");
    }
}

// ---------------- K1: fused projections -> bf16 splits + skip ----------------
__global__ __launch_bounds__(256) void proj_kernel(
    const float* __restrict__ x,
    const float* __restrict__ Wq, const float* __restrict__ bq,
    const float* __restrict__ Wk, const float* __restrict__ bk,
    const float* __restrict__ Wv, const float* __restrict__ bv,
    const float* __restrict__ Ws, const float* __restrict__ bs)
{
    __shared__ float xs[32 * 129];
    const int tid = threadIdx.x;
    const int r0  = blockIdx.x * 32;
    const float SCALE = 0.08838834764831843f;

    for (int i = tid; i < 32 * CC; i += 256) {
        int r = i >> 7, c = i & 127;
        xs[r * 129 + c] = x[(r0 + r) * CC + c];
    }
    __syncthreads();

    const int ri = (tid >> 5) * 4;
    const int c0 = (tid & 31) * 4;

    const float* Wt[4] = {Wq, Wk, Wv, Ws};
    const float* bt[4] = {bq, bk, bv, bs};

    #pragma unroll
    for (int w = 0; w < 4; w++) {
        const float* W = Wt[w];
        ull acc[4][2];
        #pragma unroll
        for (int i = 0; i < 4; i++) { acc[i][0] = 0ULL; acc[i][1] = 0ULL; }

        #pragma unroll 4
        for (int k2 = 0; k2 < CC; k2++) {
            ulonglong2 wp = *reinterpret_cast<const ulonglong2*>(W + k2 * CC + c0);
            #pragma unroll
            for (int dr = 0; dr < 4; dr++) {
                ull x2 = dup2(xs[(ri + dr) * 129 + k2]);
                acc[dr][0] = ffma2(x2, wp.x, acc[dr][0]);
                acc[dr][1] = ffma2(x2, wp.y, acc[dr][1]);
            }
        }
        float4 bb = *reinterpret_cast<const float4*>(bt[w] + c0);
        #pragma unroll
        for (int dr = 0; dr < 4; dr++) {
            float2 a0 = upk(acc[dr][0]), a1 = upk(acc[dr][1]);
            int row = r0 + ri + dr;
            float ox = a0.x + bb.x, oy = a0.y + bb.y;
            float oz = a1.x + bb.z, ow = a1.y + bb.w;
            if (w == 3) {
                float4 o = {ox, oy, oz, ow};
                *reinterpret_cast<float4*>(g_skip + row * CC + c0) = o;
            } else {
                float s = (w == 0) ? SCALE : 1.f;
                ox *= s; oy *= s; oz *= s; ow *= s;
                uint32_t lo0, hi0, lo1, hi1;
                split_pair(ox, oy, lo0, hi0);
                split_pair(oz, ow, lo1, hi1);
                __nv_bfloat16* d0 = (w == 0) ? g_qb0 : (w == 1) ? g_kb0 : g_vb0;
                __nv_bfloat16* d1 = (w == 0) ? g_qb1 : (w == 1) ? g_kb1 : g_vb1;
                uint2 u0 = {lo0, lo1};
                uint2 u1 = {hi0, hi1};
                *reinterpret_cast<uint2*>(d0 + row * CC + c0) = u0;
                *reinterpret_cast<uint2*>(d1 + row * CC + c0) = u1;
            }
        }
    }
}

// ---------------- K2: flash attention via mma.sync (bf16 2-split) ----------------
#define AQ0 0
#define AQ1 34816
#define AK0 69632
#define AK1 104448
#define AV0 139264
#define AV1 174080
#define ATTN_SMEM 208896

__global__ __launch_bounds__(256, 1) void attn_mma_kernel()
{
    extern __shared__ __align__(16) char smc[];
    const uint32_t sb = smem_u32(smc);
    const int tid  = threadIdx.x, wid = tid >> 5, lane = tid & 31;
    const int qbase = blockIdx.x * 128;
    const int kofs  = blockIdx.y * HALFN;

    ld_tile_async(sb + AQ0, g_qb0 + (size_t)qbase * CC, tid);
    ld_tile_async(sb + AQ1, g_qb1 + (size_t)qbase * CC, tid);
    CP_COMMIT();

    const int r0   = wid * 16;
    const int qrow = lane >> 2, qc = (lane & 3) * 2;
    const int gr0  = qbase + r0 + qrow, gr1 = gr0 + 8;

    const uint32_t aoff = (uint32_t)((r0 + (lane & 15)) * 272 + ((lane >> 4) & 1) * 16);
    const uint32_t boff = (uint32_t)(((lane & 7) + ((lane >> 4) & 1) * 8) * 272 + ((lane >> 3) & 1) * 16);
    const uint32_t voff = (uint32_t)(((lane & 7) + ((lane >> 3) & 1) * 8) * 272 + ((lane >> 4) & 1) * 16);

    float pv[16][4];
    #pragma unroll
    for (int i = 0; i < 16; i++)
        #pragma unroll
        for (int j = 0; j < 4; j++) pv[i][j] = 0.f;
    float l0 = 0.f, l1 = 0.f;

    CP_WAIT(0);
    __syncthreads();   // Q resident

    for (int kb = 0; kb < HALFN; kb += 128) {
        // K pair (group 1 after commit), V pair (group 0)
        ld_tile_async(sb + AK0, g_kb0 + (size_t)(kofs + kb) * CC, tid);
        ld_tile_async(sb + AK1, g_kb1 + (size_t)(kofs + kb) * CC, tid);
        CP_COMMIT();
        ld_tile_async(sb + AV0, g_vb0 + (size_t)(kofs + kb) * CC, tid);
        ld_tile_async(sb + AV1, g_vb1 + (size_t)(kofs + kb) * CC, tid);
        CP_COMMIT();
        CP_WAIT(1);        // K ready; V still in flight
        __syncthreads();

        float sc[16][4];
        #pragma unroll
        for (int i = 0; i < 16; i++)
            #pragma unroll
            for (int j = 0; j < 4; j++) sc[i][j] = 0.f;

        // scores: (q0+q1)k0 pass + q0k1 pass  (a1b1 dropped)
        #pragma unroll
        for (int kc = 0; kc < 8; kc++) {
            uint32_t a0[4], a1[4];
            ldsm4(a0, sb + AQ0 + aoff + kc * 32);
            ldsm4(a1, sb + AQ1 + aoff + kc * 32);
            #pragma unroll
            for (int nt2 = 0; nt2 < 8; nt2++) {
                uint32_t b[4];
                ldsm4(b, sb + AK0 + (uint32_t)(nt2 * 16 * 272) + boff + kc * 32);
                mma16816(sc[2 * nt2],     a0, b[0], b[1]);
                mma16816(sc[2 * nt2 + 1], a0, b[2], b[3]);
                mma16816(sc[2 * nt2],     a1, b[0], b[1]);
                mma16816(sc[2 * nt2 + 1], a1, b[2], b[3]);
            }
            #pragma unroll
            for (int nt2 = 0; nt2 < 8; nt2++) {
                uint32_t b[4];
                ldsm4(b, sb + AK1 + (uint32_t)(nt2 * 16 * 272) + boff + kc * 32);
                mma16816(sc[2 * nt2],     a0, b[0], b[1]);
                mma16816(sc[2 * nt2 + 1], a0, b[2], b[3]);
            }
        }

        // exp (no max; scores bounded), diag mask, row sums
        float rs0 = 0.f, rs1 = 0.f;
        #pragma unroll
        for (int nt = 0; nt < 16; nt++) {
            int gc = kofs + kb + nt * 8 + qc;
            float e0 = (gr0 == gc)     ? 0.f : __expf(sc[nt][0]);
            float e1 = (gr0 == gc + 1) ? 0.f : __expf(sc[nt][1]);
            float e2 = (gr1 == gc)     ? 0.f : __expf(sc[nt][2]);
            float e3 = (gr1 == gc + 1) ? 0.f : __expf(sc[nt][3]);
            sc[nt][0] = e0; sc[nt][1] = e1; sc[nt][2] = e2; sc[nt][3] = e3;
            rs0 += e0 + e1; rs1 += e2 + e3;
        }
        rs0 += __shfl_xor_sync(0xffffffffu, rs0, 1);
        rs0 += __shfl_xor_sync(0xffffffffu, rs0, 2);
        rs1 += __shfl_xor_sync(0xffffffffu, rs1, 1);
        rs1 += __shfl_xor_sync(0xffffffffu, rs1, 2);
        l0 += rs0; l1 += rs1;

        CP_WAIT(0);        // V ready
        __syncthreads();

        // PV: p0v0 + p1v0 pass, p0v1 pass
        #pragma unroll
        for (int kc = 0; kc < 8; kc++) {
            uint32_t p0[4], p1[4];
            split_pair(sc[2 * kc][0],     sc[2 * kc][1],     p0[0], p1[0]);
            split_pair(sc[2 * kc][2],     sc[2 * kc][3],     p0[1], p1[1]);
            split_pair(sc[2 * kc + 1][0], sc[2 * kc + 1][1], p0[2], p1[2]);
            split_pair(sc[2 * kc + 1][2], sc[2 * kc + 1][3], p0[3], p1[3]);
            #pragma unroll
            for (int nt2 = 0; nt2 < 8; nt2++) {
                uint32_t vf[4];
                ldsm4t(vf, sb + AV0 + (uint32_t)(kc * 16 * 272) + voff + nt2 * 32);
                mma16816(pv[2 * nt2],     p0, vf[0], vf[1]);
                mma16816(pv[2 * nt2 + 1], p0, vf[2], vf[3]);
                mma16816(pv[2 * nt2],     p1, vf[0], vf[1]);
                mma16816(pv[2 * nt2 + 1], p1, vf[2], vf[3]);
            }
            #pragma unroll
            for (int nt2 = 0; nt2 < 8; nt2++) {
                uint32_t vf[4];
                ldsm4t(vf, sb + AV1 + (uint32_t)(kc * 16 * 272) + voff + nt2 * 32);
                mma16816(pv[2 * nt2],     p0, vf[0], vf[1]);
                mma16816(pv[2 * nt2 + 1], p0, vf[2], vf[3]);
            }
        }
        __syncthreads();   // all PV reads done before next iter's cp.async writes
    }

    float* aout = g_acc + (size_t)blockIdx.y * NN * CC;
    #pragma unroll
    for (int nt = 0; nt < 16; nt++) {
        int c = nt * 8 + qc;
        *reinterpret_cast<float2*>(aout + (size_t)gr0 * CC + c) = make_float2(pv[nt][0], pv[nt][1]);
        *reinterpret_cast<float2*>(aout + (size_t)gr1 * CC + c) = make_float2(pv[nt][2], pv[nt][3]);
    }
    if ((lane & 3) == 0) {
        g_l[blockIdx.y * NN + gr0] = l0;
        g_l[blockIdx.y * NN + gr1] = l1;
    }
}

// ---------------- K3: combine halves -> h ----------------
__global__ __launch_bounds__(256) void combine_kernel()
{
    int i = blockIdx.x * 256 + threadIdx.x;
    int row = i >> 7;
    float l = g_l[row] + g_l[NN + row];
    g_h[i] = __fdividef(g_acc[i] + g_acc[NN * CC + i], l) + g_skip[i];
}

// ---------------- K4: row norms + bf16 of h (single split) ----------------
__global__ __launch_bounds__(256) void norm_split_kernel()
{
    int row  = blockIdx.x * 8 + (threadIdx.x >> 5);
    int lane = threadIdx.x & 31;
    const float* h = g_h + row * CC;
    float s = 0.f;
    for (int c = lane; c < CC; c += 32) {
        float v = h[c];
        s += v * v;
        g_hb0[row * CC + c] = __float2bfloat16_rn(v);
    }
    s += __shfl_xor_sync(0xffffffffu, s, 16);
    s += __shfl_xor_sync(0xffffffffu, s, 8);
    s += __shfl_xor_sync(0xffffffffu, s, 4);
    s += __shfl_xor_sync(0xffffffffu, s, 2);
    s += __shfl_xor_sync(0xffffffffu, s, 1);
    if (lane == 0) g_norm[row] = 0.5f * s;
}

// ---------------- K5: kNN candidates (single bf16 product; exact rescore later) ----------------
#define KQ0 0
#define KK0 34816
#define KPS 69632                // 128 x 129 f32 = 66048 B
#define KNR 135680               // 128 f32
#define KNN_SMEM 136192

__global__ __launch_bounds__(256, 1) void knn_mma_kernel()
{
    extern __shared__ __align__(16) char smc[];
    const uint32_t sb = smem_u32(smc);
    float* Ps   = reinterpret_cast<float*>(smc + KPS);
    float* nr_s = reinterpret_cast<float*>(smc + KNR);

    const int tid  = threadIdx.x, wid = tid >> 5, lane = tid & 31;
    const int qbase = blockIdx.x * 128;
    const int kofs  = blockIdx.y * HALFN;

    ld_tile_async(sb + KQ0, g_hb0 + (size_t)qbase * CC, tid);
    CP_COMMIT();

    const int r0   = wid * 16;
    const int qrow = lane >> 2, qc = (lane & 3) * 2;
    const int gr0  = qbase + r0 + qrow, gr1 = gr0 + 8;
    const int lr0  = r0 + qrow, lr1 = lr0 + 8;

    const uint32_t aoff = (uint32_t)((r0 + (lane & 15)) * 272 + ((lane >> 4) & 1) * 16);
    const uint32_t boff = (uint32_t)(((lane & 7) + ((lane >> 4) & 1) * 8) * 272 + ((lane >> 3) & 1) * 16);

    const int srow  = tid >> 1;
    const int scol0 = (tid & 1) * 64;
    float tv[NCAND]; int ti[NCAND];
    #pragma unroll
    for (int t = 0; t < NCAND; t++) { tv[t] = -3e38f; ti[t] = 0; }
    float vmin = -3e38f;

    CP_WAIT(0);
    __syncthreads();

    for (int kb = 0; kb < HALFN; kb += 128) {
        ld_tile_async(sb + KK0, g_hb0 + (size_t)(kofs + kb) * CC, tid);
        CP_COMMIT();
        if (tid < 128) nr_s[tid] = g_norm[kofs + kb + tid];
        CP_WAIT(0);
        __syncthreads();

        float sc[16][4];
        #pragma unroll
        for (int i = 0; i < 16; i++)
            #pragma unroll
            for (int j = 0; j < 4; j++) sc[i][j] = 0.f;

        #pragma unroll
        for (int kc = 0; kc < 8; kc++) {
            uint32_t a[4];
            ldsm4(a, sb + KQ0 + aoff + kc * 32);
            #pragma unroll
            for (int nt2 = 0; nt2 < 8; nt2++) {
                uint32_t b[4];
                ldsm4(b, sb + KK0 + (uint32_t)(nt2 * 16 * 272) + boff + kc * 32);
                mma16816(sc[2 * nt2],     a, b[0], b[1]);
                mma16816(sc[2 * nt2 + 1], a, b[2], b[3]);
            }
        }

        #pragma unroll
        for (int nt = 0; nt < 16; nt++) {
            int c = nt * 8 + qc;
            int gc = kofs + kb + c;
            float v0 = sc[nt][0] - nr_s[c];
            float v1 = sc[nt][1] - nr_s[c + 1];
            float v2 = sc[nt][2] - nr_s[c];
            float v3 = sc[nt][3] - nr_s[c + 1];
            if (gr0 == gc)     v0 = -3e38f;
            if (gr0 == gc + 1) v1 = -3e38f;
            if (gr1 == gc)     v2 = -3e38f;
            if (gr1 == gc + 1) v3 = -3e38f;
            Ps[lr0 * 129 + c]     = v0;
            Ps[lr0 * 129 + c + 1] = v1;
            Ps[lr1 * 129 + c]     = v2;
            Ps[lr1 * 129 + c + 1] = v3;
        }
        __syncthreads();

        const float* pr = Ps + srow * 129 + scol0;
        const int gbase = kofs + kb + scol0;
        #pragma unroll 4
        for (int j = 0; j < 64; j++) {
            float v = pr[j];
            if (v > vmin) {
                float cv = v; int cidx = gbase + j;
                #pragma unroll
                for (int t = 0; t < NCAND; t++) {
                    if (cv > tv[t]) {
                        float tmp = tv[t]; tv[t] = cv; cv = tmp;
                        int tj = ti[t]; ti[t] = cidx; cidx = tj;
                    }
                }
                vmin = tv[NCAND - 1];
            }
        }
        __syncthreads();
    }

    float* mv = Ps;
    int*   mi = reinterpret_cast<int*>(Ps + 256 * NCAND);
    #pragma unroll
    for (int t = 0; t < NCAND; t++) {
        mv[tid * NCAND + t] = tv[t];
        mi[tid * NCAND + t] = ti[t];
    }
    __syncthreads();
    if (tid < 128) {
        const float* va = mv + (2 * tid) * NCAND;
        const int*   ia = mi + (2 * tid) * NCAND;
        const float* vb = mv + (2 * tid + 1) * NCAND;
        const int*   ib = mi + (2 * tid + 1) * NCAND;
        float* outv = g_cv16 + (size_t)blockIdx.y * NN * NCAND + (size_t)(qbase + tid) * NCAND;
        int*   outi = g_ci16 + (size_t)blockIdx.y * NN * NCAND + (size_t)(qbase + tid) * NCAND;
        int a = 0, b = 0;
        #pragma unroll
        for (int t = 0; t < NCAND; t++) {
            float xa = va[a], xb = vb[b];
            bool ta = (xa > xb) || (xa == xb && ia[a] < ib[b]);
            if (ta) { outv[t] = xa; outi[t] = ia[a]; a++; }
            else    { outv[t] = xb; outi[t] = ib[b]; b++; }
        }
    }
}

// ---------------- K6: exact fp32 rescore of 32 candidates -> top-7 ----------------
__global__ __launch_bounds__(256) void knn_rescore_kernel()
{
    int node = (blockIdx.x * 256 + threadIdx.x) >> 5;
    int lane = threadIdx.x & 31;

    float4 hv = *reinterpret_cast<const float4*>(g_h + (size_t)node * CC + lane * 4);
    int half = lane >> 4, slot = lane & 15;
    int ci = g_ci16[(size_t)half * NN * NCAND + (size_t)node * NCAND + slot];

    float myv = -3e38f;
    for (int c = 0; c < 32; c++) {
        int cj = __shfl_sync(0xffffffffu, ci, c);
        float4 hc = *reinterpret_cast<const float4*>(g_h + (size_t)cj * CC + lane * 4);
        float p = hv.x * hc.x + hv.y * hc.y + hv.z * hc.z + hv.w * hc.w;
        #pragma unroll
        for (int m = 16; m >= 1; m >>= 1) p += __shfl_xor_sync(0xffffffffu, p, m);
        if (lane == c) myv = p - g_norm[cj];
    }

    float v = myv; int idx = ci;
    #pragma unroll
    for (int t = 0; t < KNBR; t++) {
        float bv = v; int bidx = idx;
        #pragma unroll
        for (int m = 16; m >= 1; m >>= 1) {
            float ov = __shfl_xor_sync(0xffffffffu, bv, m);
            int   oi = __shfl_xor_sync(0xffffffffu, bidx, m);
            if (ov > bv || (ov == bv && oi < bidx)) { bv = ov; bidx = oi; }
        }
        if (lane == 0) g_idx[node * KNBR + t] = bidx;
        if (idx == bidx) v = -3.3e38f;
    }
}

// ---------------- K7: m1 = h @ W1 ----------------
__global__ __launch_bounds__(256) void gcn1_gemm(const float* __restrict__ W1)
{
    __shared__ float xs[32 * 129];
    const int tid = threadIdx.x;
    const int r0  = blockIdx.x * 32;

    for (int i = tid; i < 32 * CC; i += 256) {
        int r = i >> 7, c = i & 127;
        xs[r * 129 + c] = g_h[(r0 + r) * CC + c];
    }
    __syncthreads();

    const int ri = (tid >> 5) * 4;
    const int c0 = (tid & 31) * 4;

    ull acc[4][2];
    #pragma unroll
    for (int i = 0; i < 4; i++) { acc[i][0] = 0ULL; acc[i][1] = 0ULL; }

    #pragma unroll 4
    for (int k2 = 0; k2 < CC; k2++) {
        ulonglong2 wp = *reinterpret_cast<const ulonglong2*>(W1 + k2 * CC + c0);
        #pragma unroll
        for (int dr = 0; dr < 4; dr++) {
            ull x2 = dup2(xs[(ri + dr) * 129 + k2]);
            acc[dr][0] = ffma2(x2, wp.x, acc[dr][0]);
            acc[dr][1] = ffma2(x2, wp.y, acc[dr][1]);
        }
    }
    #pragma unroll
    for (int dr = 0; dr < 4; dr++) {
        float2 a0 = upk(acc[dr][0]), a1 = upk(acc[dr][1]);
        float4 o = {a0.x, a0.y, a1.x, a1.y};
        *reinterpret_cast<float4*>(g_m1 + (r0 + ri + dr) * CC + c0) = o;
    }
}

// ---------------- K8: GCN layer-1 gather + relu ----------------
__global__ __launch_bounds__(128) void gather1(const float* __restrict__ b1)
{
    int node = blockIdx.x;
    int c    = threadIdx.x;
    float s = g_m1[node * CC + c];
    #pragma unroll
    for (int t = 0; t < KNBR; t++) {
        int nb = g_idx[node * KNBR + t];
        s += g_m1[nb * CC + c];
    }
    g_h1[node * CC + c] = fmaxf(s * 0.125f + b1[c], 0.f);
}

// ---------------- K9: m2 = h1 @ W2 ----------------
__global__ __launch_bounds__(256) void m2_kernel(const float* __restrict__ W2)
{
    int row  = blockIdx.x * 8 + (threadIdx.x >> 5);
    int lane = threadIdx.x & 31;
    float s = 0.f;
    for (int c = lane; c < CC; c += 32) s += g_h1[row * CC + c] * W2[c];
    s += __shfl_xor_sync(0xffffffffu, s, 16);
    s += __shfl_xor_sync(0xffffffffu, s, 8);
    s += __shfl_xor_sync(0xffffffffu, s, 4);
    s += __shfl_xor_sync(0xffffffffu, s, 2);
    s += __shfl_xor_sync(0xffffffffu, s, 1);
    if (lane == 0) g_m2[row] = s;
}

// ---------------- K10: GCN layer-2 gather -> output ----------------
__global__ __launch_bounds__(256) void out_kernel(const float* __restrict__ b2,
                                                  float* __restrict__ out)
{
    int n = blockIdx.x * 256 + threadIdx.x;
    float s = g_m2[n];
    #pragma unroll
    for (int t = 0; t < KNBR; t++) s += g_m2[g_idx[n * KNBR + t]];
    out[n] = s * 0.125f + b2[0];
}

// ---------------- launch ----------------
extern "C" void kernel_launch(void* const* d_in, const int* in_sizes, int n_in,
                              void* d_out, int out_size)
{
    const float* x   = (const float*)d_in[0];
    const float* Wq  = (const float*)d_in[1];
    const float* bq  = (const float*)d_in[2];
    const float* Wk  = (const float*)d_in[3];
    const float* bk  = (const float*)d_in[4];
    const float* Wv  = (const float*)d_in[5];
    const float* bv  = (const float*)d_in[6];
    const float* Wsk = (const float*)d_in[7];
    const float* bsk = (const float*)d_in[8];
    const float* W1  = (const float*)d_in[9];
    const float* b1  = (const float*)d_in[10];
    const float* W2  = (const float*)d_in[11];
    const float* b2  = (const float*)d_in[12];
    float* out = (float*)d_out;

    cudaFuncSetAttribute(attn_mma_kernel, cudaFuncAttributeMaxDynamicSharedMemorySize, ATTN_SMEM);
    cudaFuncSetAttribute(knn_mma_kernel,  cudaFuncAttributeMaxDynamicSharedMemorySize, KNN_SMEM);

    proj_kernel<<<NN / 32, 256>>>(x, Wq, bq, Wk, bk, Wv, bv, Wsk, bsk);
    attn_mma_kernel<<<dim3(NN / 128, 2), 256, ATTN_SMEM>>>();
    combine_kernel<<<NN * CC / 256, 256>>>();
    norm_split_kernel<<<NN / 8, 256>>>();
    knn_mma_kernel<<<dim3(NN / 128, 2), 256, KNN_SMEM>>>();
    knn_rescore_kernel<<<NN / 8, 256>>>();
    gcn1_gemm<<<NN / 32, 256>>>(W1);
    gather1<<<NN, CC>>>(b1);
    m2_kernel<<<NN / 8, 256>>>(W2);
    out_kernel<<<NN / 256, 256>>>(b2, out);
}

// round 6
// speedup vs baseline: 4.1257x; 1.1021x over previous
#include <cuda_runtime.h>
#include <cuda_bf16.h>
#include <cuda_fp16.h>
#include <cstdint>

#define NN    8192
#define CC    128
#define KNBR  7
#define HALFN 4096
#define NCAND 16

typedef unsigned long long ull;

// ---------------- device scratch ----------------
__device__ float g_skip[NN * CC];
__device__ float g_h[NN * CC];
__device__ float g_acc[2 * NN * CC];
__device__ float g_l[2 * NN];
__device__ float g_norm[NN];
__device__ float g_cv16[2 * NN * NCAND];
__device__ int   g_ci16[2 * NN * NCAND];
__device__ int   g_idx[NN * KNBR];
__device__ float g_m1[NN * CC];
__device__ float g_h1[NN * CC];
__device__ float g_m2[NN];
__device__ __nv_bfloat16 g_qb0[NN * CC], g_qb1[NN * CC];
__device__ __nv_bfloat16 g_kb0[NN * CC], g_kb1[NN * CC];
__device__ __half        g_vh[NN * CC];
__device__ __nv_bfloat16 g_hb0[NN * CC];

// ---------------- packed fp32x2 (SIMT GEMMs) ----------------
__device__ __forceinline__ ull ffma2(ull a, ull b, ull c) {
    ull d;
    asm("fma.rn.f32x2 %0, %1, %2, %3;" : "=l"(d) : "l"(a), "l"(b), "l"(c));
    return d;
}
__device__ __forceinline__ ull dup2(float x) {
    ull d;
    asm("mov.b64 %0, {%1, %1};" : "=l"(d) : "f"(x));
    return d;
}
__device__ __forceinline__ float2 upk(ull v) {
    float2 r;
    asm("mov.b64 {%0, %1}, %2;" : "=f"(r.x), "=f"(r.y) : "l"(v));
    return r;
}

// ---------------- mma / ldmatrix / cp.async helpers ----------------
__device__ __forceinline__ uint32_t smem_u32(const void* p) {
    uint32_t a;
    asm("{ .reg .u64 t; cvta.to.shared.u64 t, %1; cvt.u32.u64 %0, t; }" : "=r"(a) : "l"(p));
    return a;
}
__device__ __forceinline__ void ldsm4(uint32_t* r, uint32_t a) {
    asm volatile("ldmatrix.sync.aligned.m8n8.x4.shared.b16 {%0,%1,%2,%3}, [%4];"
                 : "=r"(r[0]), "=r"(r[1]), "=r"(r[2]), "=r"(r[3]) : "r"(a));
}
__device__ __forceinline__ void ldsm4t(uint32_t* r, uint32_t a) {
    asm volatile("ldmatrix.sync.aligned.m8n8.x4.trans.shared.b16 {%0,%1,%2,%3}, [%4];"
                 : "=r"(r[0]), "=r"(r[1]), "=r"(r[2]), "=r"(r[3]) : "r"(a));
}
__device__ __forceinline__ void mma16816(float* c, const uint32_t* a, uint32_t b0, uint32_t b1) {
    asm volatile(
        "mma.sync.aligned.m16n8k16.row.col.f32.bf16.bf16.f32 "
        "{%0,%1,%2,%3}, {%4,%5,%6,%7}, {%8,%9}, {%0,%1,%2,%3};"
        : "+f"(c[0]), "+f"(c[1]), "+f"(c[2]), "+f"(c[3])
        : "r"(a[0]), "r"(a[1]), "r"(a[2]), "r"(a[3]), "r"(b0), "r"(b1));
}
__device__ __forceinline__ void mma16816h(float* c, const uint32_t* a, uint32_t b0, uint32_t b1) {
    asm volatile(
        "mma.sync.aligned.m16n8k16.row.col.f32.f16.f16.f32 "
        "{%0,%1,%2,%3}, {%4,%5,%6,%7}, {%8,%9}, {%0,%1,%2,%3};"
        : "+f"(c[0]), "+f"(c[1]), "+f"(c[2]), "+f"(c[3])
        : "r"(a[0]), "r"(a[1]), "r"(a[2]), "r"(a[3]), "r"(b0), "r"(b1));
}
#define CP_COMMIT() asm volatile("cp.async.commit_group;" ::: "memory")
#define CP_WAIT(n)  asm volatile("cp.async.wait_group %0;" :: "n"(n) : "memory")

__device__ __forceinline__ uint32_t pack_bf(float x, float y) {
    __nv_bfloat162 t = __floats2bfloat162_rn(x, y);
    return *reinterpret_cast<uint32_t*>(&t);
}
__device__ __forceinline__ uint32_t pack_h(float x, float y) {
    __half2 t = __floats2half2_rn(x, y);
    return *reinterpret_cast<uint32_t*>(&t);
}
__device__ __forceinline__ void split_pair(float x, float y, uint32_t& p0, uint32_t& p1) {
    __nv_bfloat16 bx = __float2bfloat16_rn(x), by = __float2bfloat16_rn(y);
    __nv_bfloat162 t; t.x = bx; t.y = by;
    p0 = *reinterpret_cast<uint32_t*>(&t);
    p1 = pack_bf(x - __bfloat162float(bx), y - __bfloat162float(by));
}
__device__ __forceinline__ void split_pair_h(float x, float y, uint32_t& p0, uint32_t& p1) {
    __half hx = __float2half_rn(x), hy = __float2half_rn(y);
    __half2 t; t.x = hx; t.y = hy;
    p0 = *reinterpret_cast<uint32_t*>(&t);
    p1 = pack_h(x - __half2float(hx), y - __half2float(hy));
}
// async 128x128 16-bit tile -> smem rows of 272B
__device__ __forceinline__ void ld_tile_async(uint32_t dst, const void* __restrict__ srcv, int tid) {
    const char* src = reinterpret_cast<const char*>(srcv);
    #pragma unroll
    for (int i = 0; i < 8; i++) {
        int idx = tid + i * 256;
        int row = idx >> 4, ch = idx & 15;
        asm volatile("cp.async.cg.shared.global [%0], [%1], 16;" ::
            "r"(dst + (uint32_t)(row * 272 + ch * 16)), "l"(src + (size_t)row * CC * 2 + ch * 16) : "memory");
    }
}

// ---------------- K1: fused projections -> bf16 splits (q,k), fp16 (v), skip ----------------
__global__ __launch_bounds__(256) void proj_kernel(
    const float* __restrict__ x,
    const float* __restrict__ Wq, const float* __restrict__ bq,
    const float* __restrict__ Wk, const float* __restrict__ bk,
    const float* __restrict__ Wv, const float* __restrict__ bv,
    const float* __restrict__ Ws, const float* __restrict__ bs)
{
    __shared__ float xs[32 * 129];
    const int tid = threadIdx.x;
    const int r0  = blockIdx.x * 32;
    const float SCALE = 0.08838834764831843f;

    for (int i = tid; i < 32 * CC; i += 256) {
        int r = i >> 7, c = i & 127;
        xs[r * 129 + c] = x[(r0 + r) * CC + c];
    }
    __syncthreads();

    const int ri = (tid >> 5) * 4;
    const int c0 = (tid & 31) * 4;

    const float* Wt[4] = {Wq, Wk, Wv, Ws};
    const float* bt[4] = {bq, bk, bv, bs};

    #pragma unroll
    for (int w = 0; w < 4; w++) {
        const float* W = Wt[w];
        ull acc[4][2];
        #pragma unroll
        for (int i = 0; i < 4; i++) { acc[i][0] = 0ULL; acc[i][1] = 0ULL; }

        #pragma unroll 4
        for (int k2 = 0; k2 < CC; k2++) {
            ulonglong2 wp = *reinterpret_cast<const ulonglong2*>(W + k2 * CC + c0);
            #pragma unroll
            for (int dr = 0; dr < 4; dr++) {
                ull x2 = dup2(xs[(ri + dr) * 129 + k2]);
                acc[dr][0] = ffma2(x2, wp.x, acc[dr][0]);
                acc[dr][1] = ffma2(x2, wp.y, acc[dr][1]);
            }
        }
        float4 bb = *reinterpret_cast<const float4*>(bt[w] + c0);
        #pragma unroll
        for (int dr = 0; dr < 4; dr++) {
            float2 a0 = upk(acc[dr][0]), a1 = upk(acc[dr][1]);
            int row = r0 + ri + dr;
            float ox = a0.x + bb.x, oy = a0.y + bb.y;
            float oz = a1.x + bb.z, ow = a1.y + bb.w;
            if (w == 3) {
                float4 o = {ox, oy, oz, ow};
                *reinterpret_cast<float4*>(g_skip + row * CC + c0) = o;
            } else if (w == 2) {
                uint2 u = {pack_h(ox, oy), pack_h(oz, ow)};
                *reinterpret_cast<uint2*>(g_vh + row * CC + c0) = u;
            } else {
                float s = (w == 0) ? SCALE : 1.f;
                ox *= s; oy *= s; oz *= s; ow *= s;
                uint32_t lo0, hi0, lo1, hi1;
                split_pair(ox, oy, lo0, hi0);
                split_pair(oz, ow, lo1, hi1);
                __nv_bfloat16* d0 = (w == 0) ? g_qb0 : g_kb0;
                __nv_bfloat16* d1 = (w == 0) ? g_qb1 : g_kb1;
                uint2 u0 = {lo0, lo1};
                uint2 u1 = {hi0, hi1};
                *reinterpret_cast<uint2*>(d0 + row * CC + c0) = u0;
                *reinterpret_cast<uint2*>(d1 + row * CC + c0) = u1;
            }
        }
    }
}

// ---------------- K2: flash attention (bf16 3-prod scores, fp16 2-prod PV) ----------------
#define AQ0 0
#define AQ1 34816
#define AK0 69632
#define AK1 104448
#define AV0 139264
#define ATTN_SMEM 174080

__global__ __launch_bounds__(256, 1) void attn_mma_kernel()
{
    extern __shared__ __align__(16) char smc[];
    const uint32_t sb = smem_u32(smc);
    const int tid  = threadIdx.x, wid = tid >> 5, lane = tid & 31;
    const int qbase = blockIdx.x * 128;
    const int kofs  = blockIdx.y * HALFN;

    ld_tile_async(sb + AQ0, g_qb0 + (size_t)qbase * CC, tid);
    ld_tile_async(sb + AQ1, g_qb1 + (size_t)qbase * CC, tid);
    CP_COMMIT();

    const int r0   = wid * 16;
    const int qrow = lane >> 2, qc = (lane & 3) * 2;
    const int gr0  = qbase + r0 + qrow, gr1 = gr0 + 8;

    const uint32_t aoff = (uint32_t)((r0 + (lane & 15)) * 272 + ((lane >> 4) & 1) * 16);
    const uint32_t boff = (uint32_t)(((lane & 7) + ((lane >> 4) & 1) * 8) * 272 + ((lane >> 3) & 1) * 16);
    const uint32_t voff = (uint32_t)(((lane & 7) + ((lane >> 3) & 1) * 8) * 272 + ((lane >> 4) & 1) * 16);

    float pv[16][4];
    #pragma unroll
    for (int i = 0; i < 16; i++)
        #pragma unroll
        for (int j = 0; j < 4; j++) pv[i][j] = 0.f;
    float l0 = 0.f, l1 = 0.f;

    CP_WAIT(0);
    __syncthreads();   // Q resident

    for (int kb = 0; kb < HALFN; kb += 128) {
        ld_tile_async(sb + AK0, g_kb0 + (size_t)(kofs + kb) * CC, tid);
        ld_tile_async(sb + AK1, g_kb1 + (size_t)(kofs + kb) * CC, tid);
        CP_COMMIT();
        ld_tile_async(sb + AV0, g_vh + (size_t)(kofs + kb) * CC, tid);
        CP_COMMIT();
        CP_WAIT(1);        // K ready; V in flight
        __syncthreads();

        float sc[16][4];
        #pragma unroll
        for (int i = 0; i < 16; i++)
            #pragma unroll
            for (int j = 0; j < 4; j++) sc[i][j] = 0.f;

        // scores: (q0+q1)k0 + q0k1
        #pragma unroll
        for (int kc = 0; kc < 8; kc++) {
            uint32_t a0[4], a1[4];
            ldsm4(a0, sb + AQ0 + aoff + kc * 32);
            ldsm4(a1, sb + AQ1 + aoff + kc * 32);
            #pragma unroll
            for (int nt2 = 0; nt2 < 8; nt2++) {
                uint32_t b[4];
                ldsm4(b, sb + AK0 + (uint32_t)(nt2 * 16 * 272) + boff + kc * 32);
                mma16816(sc[2 * nt2],     a0, b[0], b[1]);
                mma16816(sc[2 * nt2 + 1], a0, b[2], b[3]);
                mma16816(sc[2 * nt2],     a1, b[0], b[1]);
                mma16816(sc[2 * nt2 + 1], a1, b[2], b[3]);
            }
            #pragma unroll
            for (int nt2 = 0; nt2 < 8; nt2++) {
                uint32_t b[4];
                ldsm4(b, sb + AK1 + (uint32_t)(nt2 * 16 * 272) + boff + kc * 32);
                mma16816(sc[2 * nt2],     a0, b[0], b[1]);
                mma16816(sc[2 * nt2 + 1], a0, b[2], b[3]);
            }
        }

        // exp (no max; scores bounded), diag mask, row sums
        float rs0 = 0.f, rs1 = 0.f;
        #pragma unroll
        for (int nt = 0; nt < 16; nt++) {
            int gc = kofs + kb + nt * 8 + qc;
            float e0 = (gr0 == gc)     ? 0.f : __expf(sc[nt][0]);
            float e1 = (gr0 == gc + 1) ? 0.f : __expf(sc[nt][1]);
            float e2 = (gr1 == gc)     ? 0.f : __expf(sc[nt][2]);
            float e3 = (gr1 == gc + 1) ? 0.f : __expf(sc[nt][3]);
            sc[nt][0] = e0; sc[nt][1] = e1; sc[nt][2] = e2; sc[nt][3] = e3;
            rs0 += e0 + e1; rs1 += e2 + e3;
        }
        rs0 += __shfl_xor_sync(0xffffffffu, rs0, 1);
        rs0 += __shfl_xor_sync(0xffffffffu, rs0, 2);
        rs1 += __shfl_xor_sync(0xffffffffu, rs1, 1);
        rs1 += __shfl_xor_sync(0xffffffffu, rs1, 2);
        l0 += rs0; l1 += rs1;

        CP_WAIT(0);        // V ready
        __syncthreads();

        // PV: fp16, p = p0 + p1 (2 products), single V tile
        #pragma unroll
        for (int kc = 0; kc < 8; kc++) {
            uint32_t p0[4], p1[4];
            split_pair_h(sc[2 * kc][0],     sc[2 * kc][1],     p0[0], p1[0]);
            split_pair_h(sc[2 * kc][2],     sc[2 * kc][3],     p0[1], p1[1]);
            split_pair_h(sc[2 * kc + 1][0], sc[2 * kc + 1][1], p0[2], p1[2]);
            split_pair_h(sc[2 * kc + 1][2], sc[2 * kc + 1][3], p0[3], p1[3]);
            #pragma unroll
            for (int nt2 = 0; nt2 < 8; nt2++) {
                uint32_t vf[4];
                ldsm4t(vf, sb + AV0 + (uint32_t)(kc * 16 * 272) + voff + nt2 * 32);
                mma16816h(pv[2 * nt2],     p0, vf[0], vf[1]);
                mma16816h(pv[2 * nt2 + 1], p0, vf[2], vf[3]);
                mma16816h(pv[2 * nt2],     p1, vf[0], vf[1]);
                mma16816h(pv[2 * nt2 + 1], p1, vf[2], vf[3]);
            }
        }
        __syncthreads();   // PV reads done before next tile's cp.async
    }

    float* aout = g_acc + (size_t)blockIdx.y * NN * CC;
    #pragma unroll
    for (int nt = 0; nt < 16; nt++) {
        int c = nt * 8 + qc;
        *reinterpret_cast<float2*>(aout + (size_t)gr0 * CC + c) = make_float2(pv[nt][0], pv[nt][1]);
        *reinterpret_cast<float2*>(aout + (size_t)gr1 * CC + c) = make_float2(pv[nt][2], pv[nt][3]);
    }
    if ((lane & 3) == 0) {
        g_l[blockIdx.y * NN + gr0] = l0;
        g_l[blockIdx.y * NN + gr1] = l1;
    }
}

// ---------------- K3: fused combine + norm + bf16 split ----------------
__global__ __launch_bounds__(256) void combine_norm_kernel()
{
    int row  = blockIdx.x * 8 + (threadIdx.x >> 5);
    int lane = threadIdx.x & 31;
    size_t base = (size_t)row * CC + lane * 4;

    float inv = __fdividef(1.f, g_l[row] + g_l[NN + row]);
    float4 a0 = *reinterpret_cast<const float4*>(g_acc + base);
    float4 a1 = *reinterpret_cast<const float4*>(g_acc + NN * CC + base);
    float4 sk = *reinterpret_cast<const float4*>(g_skip + base);

    float4 h;
    h.x = (a0.x + a1.x) * inv + sk.x;
    h.y = (a0.y + a1.y) * inv + sk.y;
    h.z = (a0.z + a1.z) * inv + sk.z;
    h.w = (a0.w + a1.w) * inv + sk.w;
    *reinterpret_cast<float4*>(g_h + base) = h;

    uint2 hb = {pack_bf(h.x, h.y), pack_bf(h.z, h.w)};
    *reinterpret_cast<uint2*>(g_hb0 + base) = hb;

    float s = h.x * h.x + h.y * h.y + h.z * h.z + h.w * h.w;
    s += __shfl_xor_sync(0xffffffffu, s, 16);
    s += __shfl_xor_sync(0xffffffffu, s, 8);
    s += __shfl_xor_sync(0xffffffffu, s, 4);
    s += __shfl_xor_sync(0xffffffffu, s, 2);
    s += __shfl_xor_sync(0xffffffffu, s, 1);
    if (lane == 0) g_norm[row] = 0.5f * s;
}

// ---------------- K4: kNN candidates (single bf16 product; exact rescore later) ----------------
#define KQ0 0
#define KK0 34816
#define KPS 69632                // 128 x 129 f32
#define KNR 135680
#define KNN_SMEM 136192

__global__ __launch_bounds__(256, 1) void knn_mma_kernel()
{
    extern __shared__ __align__(16) char smc[];
    const uint32_t sb = smem_u32(smc);
    float* Ps   = reinterpret_cast<float*>(smc + KPS);
    float* nr_s = reinterpret_cast<float*>(smc + KNR);

    const int tid  = threadIdx.x, wid = tid >> 5, lane = tid & 31;
    const int qbase = blockIdx.x * 128;
    const int kofs  = blockIdx.y * HALFN;

    ld_tile_async(sb + KQ0, g_hb0 + (size_t)qbase * CC, tid);
    CP_COMMIT();

    const int r0   = wid * 16;
    const int qrow = lane >> 2, qc = (lane & 3) * 2;
    const int gr0  = qbase + r0 + qrow, gr1 = gr0 + 8;
    const int lr0  = r0 + qrow, lr1 = lr0 + 8;

    const uint32_t aoff = (uint32_t)((r0 + (lane & 15)) * 272 + ((lane >> 4) & 1) * 16);
    const uint32_t boff = (uint32_t)(((lane & 7) + ((lane >> 4) & 1) * 8) * 272 + ((lane >> 3) & 1) * 16);

    const int srow  = tid >> 1;
    const int scol0 = (tid & 1) * 64;
    float tv[NCAND]; int ti[NCAND];
    #pragma unroll
    for (int t = 0; t < NCAND; t++) { tv[t] = -3e38f; ti[t] = 0; }
    float vmin = -3e38f;

    CP_WAIT(0);
    __syncthreads();

    for (int kb = 0; kb < HALFN; kb += 128) {
        ld_tile_async(sb + KK0, g_hb0 + (size_t)(kofs + kb) * CC, tid);
        CP_COMMIT();
        if (tid < 128) nr_s[tid] = g_norm[kofs + kb + tid];
        CP_WAIT(0);
        __syncthreads();

        float sc[16][4];
        #pragma unroll
        for (int i = 0; i < 16; i++)
            #pragma unroll
            for (int j = 0; j < 4; j++) sc[i][j] = 0.f;

        #pragma unroll
        for (int kc = 0; kc < 8; kc++) {
            uint32_t a[4];
            ldsm4(a, sb + KQ0 + aoff + kc * 32);
            #pragma unroll
            for (int nt2 = 0; nt2 < 8; nt2++) {
                uint32_t b[4];
                ldsm4(b, sb + KK0 + (uint32_t)(nt2 * 16 * 272) + boff + kc * 32);
                mma16816(sc[2 * nt2],     a, b[0], b[1]);
                mma16816(sc[2 * nt2 + 1], a, b[2], b[3]);
            }
        }

        #pragma unroll
        for (int nt = 0; nt < 16; nt++) {
            int c = nt * 8 + qc;
            int gc = kofs + kb + c;
            float v0 = sc[nt][0] - nr_s[c];
            float v1 = sc[nt][1] - nr_s[c + 1];
            float v2 = sc[nt][2] - nr_s[c];
            float v3 = sc[nt][3] - nr_s[c + 1];
            if (gr0 == gc)     v0 = -3e38f;
            if (gr0 == gc + 1) v1 = -3e38f;
            if (gr1 == gc)     v2 = -3e38f;
            if (gr1 == gc + 1) v3 = -3e38f;
            Ps[lr0 * 129 + c]     = v0;
            Ps[lr0 * 129 + c + 1] = v1;
            Ps[lr1 * 129 + c]     = v2;
            Ps[lr1 * 129 + c + 1] = v3;
        }
        __syncthreads();

        const float* pr = Ps + srow * 129 + scol0;
        const int gbase = kofs + kb + scol0;
        #pragma unroll 4
        for (int j = 0; j < 64; j++) {
            float v = pr[j];
            if (v > vmin) {
                float cv = v; int cidx = gbase + j;
                #pragma unroll
                for (int t = 0; t < NCAND; t++) {
                    if (cv > tv[t]) {
                        float tmp = tv[t]; tv[t] = cv; cv = tmp;
                        int tj = ti[t]; ti[t] = cidx; cidx = tj;
                    }
                }
                vmin = tv[NCAND - 1];
            }
        }
        __syncthreads();
    }

    float* mv = Ps;
    int*   mi = reinterpret_cast<int*>(Ps + 256 * NCAND);
    #pragma unroll
    for (int t = 0; t < NCAND; t++) {
        mv[tid * NCAND + t] = tv[t];
        mi[tid * NCAND + t] = ti[t];
    }
    __syncthreads();
    if (tid < 128) {
        const float* va = mv + (2 * tid) * NCAND;
        const int*   ia = mi + (2 * tid) * NCAND;
        const float* vb = mv + (2 * tid + 1) * NCAND;
        const int*   ib = mi + (2 * tid + 1) * NCAND;
        float* outv = g_cv16 + (size_t)blockIdx.y * NN * NCAND + (size_t)(qbase + tid) * NCAND;
        int*   outi = g_ci16 + (size_t)blockIdx.y * NN * NCAND + (size_t)(qbase + tid) * NCAND;
        int a = 0, b = 0;
        #pragma unroll
        for (int t = 0; t < NCAND; t++) {
            float xa = va[a], xb = vb[b];
            bool ta = (xa > xb) || (xa == xb && ia[a] < ib[b]);
            if (ta) { outv[t] = xa; outi[t] = ia[a]; a++; }
            else    { outv[t] = xb; outi[t] = ib[b]; b++; }
        }
    }
}

// ---------------- K5: exact fp32 rescore of 32 candidates -> top-7 ----------------
__global__ __launch_bounds__(256) void knn_rescore_kernel()
{
    int node = (blockIdx.x * 256 + threadIdx.x) >> 5;
    int lane = threadIdx.x & 31;

    float4 hv = *reinterpret_cast<const float4*>(g_h + (size_t)node * CC + lane * 4);
    int half = lane >> 4, slot = lane & 15;
    int ci = g_ci16[(size_t)half * NN * NCAND + (size_t)node * NCAND + slot];

    float myv = -3e38f;
    for (int c = 0; c < 32; c++) {
        int cj = __shfl_sync(0xffffffffu, ci, c);
        float4 hc = *reinterpret_cast<const float4*>(g_h + (size_t)cj * CC + lane * 4);
        float p = hv.x * hc.x + hv.y * hc.y + hv.z * hc.z + hv.w * hc.w;
        #pragma unroll
        for (int m = 16; m >= 1; m >>= 1) p += __shfl_xor_sync(0xffffffffu, p, m);
        if (lane == c) myv = p - g_norm[cj];
    }

    float v = myv; int idx = ci;
    #pragma unroll
    for (int t = 0; t < KNBR; t++) {
        float bv = v; int bidx = idx;
        #pragma unroll
        for (int m = 16; m >= 1; m >>= 1) {
            float ov = __shfl_xor_sync(0xffffffffu, bv, m);
            int   oi = __shfl_xor_sync(0xffffffffu, bidx, m);
            if (ov > bv || (ov == bv && oi < bidx)) { bv = ov; bidx = oi; }
        }
        if (lane == 0) g_idx[node * KNBR + t] = bidx;
        if (idx == bidx) v = -3.3e38f;
    }
}

// ---------------- K6: m1 = h @ W1 ----------------
__global__ __launch_bounds__(256) void gcn1_gemm(const float* __restrict__ W1)
{
    __shared__ float xs[32 * 129];
    const int tid = threadIdx.x;
    const int r0  = blockIdx.x * 32;

    for (int i = tid; i < 32 * CC; i += 256) {
        int r = i >> 7, c = i & 127;
        xs[r * 129 + c] = g_h[(r0 + r) * CC + c];
    }
    __syncthreads();

    const int ri = (tid >> 5) * 4;
    const int c0 = (tid & 31) * 4;

    ull acc[4][2];
    #pragma unroll
    for (int i = 0; i < 4; i++) { acc[i][0] = 0ULL; acc[i][1] = 0ULL; }

    #pragma unroll 4
    for (int k2 = 0; k2 < CC; k2++) {
        ulonglong2 wp = *reinterpret_cast<const ulonglong2*>(W1 + k2 * CC + c0);
        #pragma unroll
        for (int dr = 0; dr < 4; dr++) {
            ull x2 = dup2(xs[(ri + dr) * 129 + k2]);
            acc[dr][0] = ffma2(x2, wp.x, acc[dr][0]);
            acc[dr][1] = ffma2(x2, wp.y, acc[dr][1]);
        }
    }
    #pragma unroll
    for (int dr = 0; dr < 4; dr++) {
        float2 a0 = upk(acc[dr][0]), a1 = upk(acc[dr][1]);
        float4 o = {a0.x, a0.y, a1.x, a1.y};
        *reinterpret_cast<float4*>(g_m1 + (r0 + ri + dr) * CC + c0) = o;
    }
}

// ---------------- K7: GCN layer-1 gather + relu ----------------
__global__ __launch_bounds__(128) void gather1(const float* __restrict__ b1)
{
    int node = blockIdx.x;
    int c    = threadIdx.x;
    float s = g_m1[node * CC + c];
    #pragma unroll
    for (int t = 0; t < KNBR; t++) {
        int nb = g_idx[node * KNBR + t];
        s += g_m1[nb * CC + c];
    }
    g_h1[node * CC + c] = fmaxf(s * 0.125f + b1[c], 0.f);
}

// ---------------- K8: m2 = h1 @ W2 ----------------
__global__ __launch_bounds__(256) void m2_kernel(const float* __restrict__ W2)
{
    int row  = blockIdx.x * 8 + (threadIdx.x >> 5);
    int lane = threadIdx.x & 31;
    float s = 0.f;
    for (int c = lane; c < CC; c += 32) s += g_h1[row * CC + c] * W2[c];
    s += __shfl_xor_sync(0xffffffffu, s, 16);
    s += __shfl_xor_sync(0xffffffffu, s, 8);
    s += __shfl_xor_sync(0xffffffffu, s, 4);
    s += __shfl_xor_sync(0xffffffffu, s, 2);
    s += __shfl_xor_sync(0xffffffffu, s, 1);
    if (lane == 0) g_m2[row] = s;
}

// ---------------- K9: GCN layer-2 gather -> output ----------------
__global__ __launch_bounds__(256) void out_kernel(const float* __restrict__ b2,
                                                  float* __restrict__ out)
{
    int n = blockIdx.x * 256 + threadIdx.x;
    float s = g_m2[n];
    #pragma unroll
    for (int t = 0; t < KNBR; t++) s += g_m2[g_idx[n * KNBR + t]];
    out[n] = s * 0.125f + b2[0];
}

// ---------------- launch ----------------
extern "C" void kernel_launch(void* const* d_in, const int* in_sizes, int n_in,
                              void* d_out, int out_size)
{
    const float* x   = (const float*)d_in[0];
    const float* Wq  = (const float*)d_in[1];
    const float* bq  = (const float*)d_in[2];
    const float* Wk  = (const float*)d_in[3];
    const float* bk  = (const float*)d_in[4];
    const float* Wv  = (const float*)d_in[5];
    const float* bv  = (const float*)d_in[6];
    const float* Wsk = (const float*)d_in[7];
    const float* bsk = (const float*)d_in[8];
    const float* W1  = (const float*)d_in[9];
    const float* b1  = (const float*)d_in[10];
    const float* W2  = (const float*)d_in[11];
    const float* b2  = (const float*)d_in[12];
    float* out = (float*)d_out;

    cudaFuncSetAttribute(attn_mma_kernel, cudaFuncAttributeMaxDynamicSharedMemorySize, ATTN_SMEM);
    cudaFuncSetAttribute(knn_mma_kernel,  cudaFuncAttributeMaxDynamicSharedMemorySize, KNN_SMEM);

    proj_kernel<<<NN / 32, 256>>>(x, Wq, bq, Wk, bk, Wv, bv, Wsk, bsk);
    attn_mma_kernel<<<dim3(NN / 128, 2), 256, ATTN_SMEM>>>();
    combine_norm_kernel<<<NN / 8, 256>>>();
    knn_mma_kernel<<<dim3(NN / 128, 2), 256, KNN_SMEM>>>();
    knn_rescore_kernel<<<NN / 8, 256>>>();
    gcn1_gemm<<<NN / 32, 256>>>(W1);
    gather1<<<NN, CC>>>(b1);
    m2_kernel<<<NN / 8, 256>>>(W2);
    out_kernel<<<NN / 256, 256>>>(b2, out);
}

// round 7
// speedup vs baseline: 4.9643x; 1.2033x over previous
#include <cuda_runtime.h>
#include <cuda_bf16.h>
#include <cuda_fp16.h>
#include <cstdint>

#define NN    8192
#define CC    128
#define KNBR  7
#define HALFN 4096
#define NCAND 16

typedef unsigned long long ull;

// ---------------- device scratch ----------------
__device__ float g_skip[NN * CC];
__device__ float g_h[NN * CC];
__device__ float g_acc[2 * NN * CC];
__device__ float g_l[2 * NN];
__device__ float g_norm[NN];
__device__ float g_cv16[2 * NN * NCAND];
__device__ int   g_ci16[2 * NN * NCAND];
__device__ int   g_idx[NN * KNBR];
__device__ float g_m1[NN * CC];
__device__ float g_h1[NN * CC];
__device__ float g_m2[NN];
__device__ __nv_bfloat16 g_qb0[NN * CC], g_qb1[NN * CC];
__device__ __nv_bfloat16 g_kb0[NN * CC], g_kb1[NN * CC];
__device__ __half        g_vh[NN * CC];
__device__ __nv_bfloat16 g_hb0[NN * CC];

// ---------------- packed fp32x2 (SIMT GEMMs) ----------------
__device__ __forceinline__ ull ffma2(ull a, ull b, ull c) {
    ull d;
    asm("fma.rn.f32x2 %0, %1, %2, %3;" : "=l"(d) : "l"(a), "l"(b), "l"(c));
    return d;
}
__device__ __forceinline__ ull dup2(float x) {
    ull d;
    asm("mov.b64 %0, {%1, %1};" : "=l"(d) : "f"(x));
    return d;
}
__device__ __forceinline__ float2 upk(ull v) {
    float2 r;
    asm("mov.b64 {%0, %1}, %2;" : "=f"(r.x), "=f"(r.y) : "l"(v));
    return r;
}

// ---------------- mma / ldmatrix / cp.async helpers ----------------
__device__ __forceinline__ uint32_t smem_u32(const void* p) {
    uint32_t a;
    asm("{ .reg .u64 t; cvta.to.shared.u64 t, %1; cvt.u32.u64 %0, t; }" : "=r"(a) : "l"(p));
    return a;
}
__device__ __forceinline__ void ldsm4(uint32_t* r, uint32_t a) {
    asm volatile("ldmatrix.sync.aligned.m8n8.x4.shared.b16 {%0,%1,%2,%3}, [%4];"
                 : "=r"(r[0]), "=r"(r[1]), "=r"(r[2]), "=r"(r[3]) : "r"(a));
}
__device__ __forceinline__ void ldsm4t(uint32_t* r, uint32_t a) {
    asm volatile("ldmatrix.sync.aligned.m8n8.x4.trans.shared.b16 {%0,%1,%2,%3}, [%4];"
                 : "=r"(r[0]), "=r"(r[1]), "=r"(r[2]), "=r"(r[3]) : "r"(a));
}
__device__ __forceinline__ void mma16816(float* c, const uint32_t* a, uint32_t b0, uint32_t b1) {
    asm volatile(
        "mma.sync.aligned.m16n8k16.row.col.f32.bf16.bf16.f32 "
        "{%0,%1,%2,%3}, {%4,%5,%6,%7}, {%8,%9}, {%0,%1,%2,%3};"
        : "+f"(c[0]), "+f"(c[1]), "+f"(c[2]), "+f"(c[3])
        : "r"(a[0]), "r"(a[1]), "r"(a[2]), "r"(a[3]), "r"(b0), "r"(b1));
}
__device__ __forceinline__ void mma16816h(float* c, const uint32_t* a, uint32_t b0, uint32_t b1) {
    asm volatile(
        "mma.sync.aligned.m16n8k16.row.col.f32.f16.f16.f32 "
        "{%0,%1,%2,%3}, {%4,%5,%6,%7}, {%8,%9}, {%0,%1,%2,%3};"
        : "+f"(c[0]), "+f"(c[1]), "+f"(c[2]), "+f"(c[3])
        : "r"(a[0]), "r"(a[1]), "r"(a[2]), "r"(a[3]), "r"(b0), "r"(b1));
}
#define CP_COMMIT() asm volatile("cp.async.commit_group;" ::: "memory")
#define CP_WAIT(n)  asm volatile("cp.async.wait_group %0;" :: "n"(n) : "memory")

__device__ __forceinline__ uint32_t pack_bf(float x, float y) {
    __nv_bfloat162 t = __floats2bfloat162_rn(x, y);
    return *reinterpret_cast<uint32_t*>(&t);
}
__device__ __forceinline__ uint32_t pack_h(float x, float y) {
    __half2 t = __floats2half2_rn(x, y);
    return *reinterpret_cast<uint32_t*>(&t);
}
__device__ __forceinline__ void split_pair(float x, float y, uint32_t& p0, uint32_t& p1) {
    __nv_bfloat16 bx = __float2bfloat16_rn(x), by = __float2bfloat16_rn(y);
    __nv_bfloat162 t; t.x = bx; t.y = by;
    p0 = *reinterpret_cast<uint32_t*>(&t);
    p1 = pack_bf(x - __bfloat162float(bx), y - __bfloat162float(by));
}
__device__ __forceinline__ void split_pair_h(float x, float y, uint32_t& p0, uint32_t& p1) {
    __half hx = __float2half_rn(x), hy = __float2half_rn(y);
    __half2 t; t.x = hx; t.y = hy;
    p0 = *reinterpret_cast<uint32_t*>(&t);
    p1 = pack_h(x - __half2float(hx), y - __half2float(hy));
}
// async 128x128 16-bit tile -> smem rows of 272B
__device__ __forceinline__ void ld_tile_async(uint32_t dst, const void* __restrict__ srcv, int tid) {
    const char* src = reinterpret_cast<const char*>(srcv);
    #pragma unroll
    for (int i = 0; i < 8; i++) {
        int idx = tid + i * 256;
        int row = idx >> 4, ch = idx & 15;
        asm volatile("cp.async.cg.shared.global [%0], [%1], 16;" ::
            "r"(dst + (uint32_t)(row * 272 + ch * 16)), "l"(src + (size_t)row * CC * 2 + ch * 16) : "memory");
    }
}
// register top-8 insert (precondition: v beats tv[7])
__device__ __forceinline__ void ins8(float* tv, int* ti, float v, int idx) {
    #pragma unroll
    for (int t = 0; t < 8; t++) {
        if (v > tv[t]) {
            float a = tv[t]; tv[t] = v; v = a;
            int   b = ti[t]; ti[t] = idx; idx = b;
        }
    }
}

// ---------------- K1: fused projections -> bf16 splits (q,k), fp16 (v), skip ----------------
__global__ __launch_bounds__(256) void proj_kernel(
    const float* __restrict__ x,
    const float* __restrict__ Wq, const float* __restrict__ bq,
    const float* __restrict__ Wk, const float* __restrict__ bk,
    const float* __restrict__ Wv, const float* __restrict__ bv,
    const float* __restrict__ Ws, const float* __restrict__ bs)
{
    __shared__ float xs[32 * 129];
    const int tid = threadIdx.x;
    const int r0  = blockIdx.x * 32;
    const float SCALE = 0.08838834764831843f;

    for (int i = tid; i < 32 * CC; i += 256) {
        int r = i >> 7, c = i & 127;
        xs[r * 129 + c] = x[(r0 + r) * CC + c];
    }
    __syncthreads();

    const int ri = (tid >> 5) * 4;
    const int c0 = (tid & 31) * 4;

    const float* Wt[4] = {Wq, Wk, Wv, Ws};
    const float* bt[4] = {bq, bk, bv, bs};

    #pragma unroll
    for (int w = 0; w < 4; w++) {
        const float* W = Wt[w];
        ull acc[4][2];
        #pragma unroll
        for (int i = 0; i < 4; i++) { acc[i][0] = 0ULL; acc[i][1] = 0ULL; }

        #pragma unroll 4
        for (int k2 = 0; k2 < CC; k2++) {
            ulonglong2 wp = *reinterpret_cast<const ulonglong2*>(W + k2 * CC + c0);
            #pragma unroll
            for (int dr = 0; dr < 4; dr++) {
                ull x2 = dup2(xs[(ri + dr) * 129 + k2]);
                acc[dr][0] = ffma2(x2, wp.x, acc[dr][0]);
                acc[dr][1] = ffma2(x2, wp.y, acc[dr][1]);
            }
        }
        float4 bb = *reinterpret_cast<const float4*>(bt[w] + c0);
        #pragma unroll
        for (int dr = 0; dr < 4; dr++) {
            float2 a0 = upk(acc[dr][0]), a1 = upk(acc[dr][1]);
            int row = r0 + ri + dr;
            float ox = a0.x + bb.x, oy = a0.y + bb.y;
            float oz = a1.x + bb.z, ow = a1.y + bb.w;
            if (w == 3) {
                float4 o = {ox, oy, oz, ow};
                *reinterpret_cast<float4*>(g_skip + row * CC + c0) = o;
            } else if (w == 2) {
                uint2 u = {pack_h(ox, oy), pack_h(oz, ow)};
                *reinterpret_cast<uint2*>(g_vh + row * CC + c0) = u;
            } else {
                float s = (w == 0) ? SCALE : 1.f;
                ox *= s; oy *= s; oz *= s; ow *= s;
                uint32_t lo0, hi0, lo1, hi1;
                split_pair(ox, oy, lo0, hi0);
                split_pair(oz, ow, lo1, hi1);
                __nv_bfloat16* d0 = (w == 0) ? g_qb0 : g_kb0;
                __nv_bfloat16* d1 = (w == 0) ? g_qb1 : g_kb1;
                uint2 u0 = {lo0, lo1};
                uint2 u1 = {hi0, hi1};
                *reinterpret_cast<uint2*>(d0 + row * CC + c0) = u0;
                *reinterpret_cast<uint2*>(d1 + row * CC + c0) = u1;
            }
        }
    }
}

// ---------------- K2: flash attention (bf16 3-prod scores, fp16 2-prod PV) ----------------
#define AQ0 0
#define AQ1 34816
#define AK0 69632
#define AK1 104448
#define AV0 139264
#define ATTN_SMEM 174080

__global__ __launch_bounds__(256, 1) void attn_mma_kernel()
{
    extern __shared__ __align__(16) char smc[];
    const uint32_t sb = smem_u32(smc);
    const int tid  = threadIdx.x, wid = tid >> 5, lane = tid & 31;
    const int qbase = blockIdx.x * 128;
    const int kofs  = blockIdx.y * HALFN;

    ld_tile_async(sb + AQ0, g_qb0 + (size_t)qbase * CC, tid);
    ld_tile_async(sb + AQ1, g_qb1 + (size_t)qbase * CC, tid);
    CP_COMMIT();

    const int r0   = wid * 16;
    const int qrow = lane >> 2, qc = (lane & 3) * 2;
    const int gr0  = qbase + r0 + qrow, gr1 = gr0 + 8;

    const uint32_t aoff = (uint32_t)((r0 + (lane & 15)) * 272 + ((lane >> 4) & 1) * 16);
    const uint32_t boff = (uint32_t)(((lane & 7) + ((lane >> 4) & 1) * 8) * 272 + ((lane >> 3) & 1) * 16);
    const uint32_t voff = (uint32_t)(((lane & 7) + ((lane >> 3) & 1) * 8) * 272 + ((lane >> 4) & 1) * 16);

    float pv[16][4];
    #pragma unroll
    for (int i = 0; i < 16; i++)
        #pragma unroll
        for (int j = 0; j < 4; j++) pv[i][j] = 0.f;
    float l0 = 0.f, l1 = 0.f;

    CP_WAIT(0);
    __syncthreads();   // Q resident

    for (int kb = 0; kb < HALFN; kb += 128) {
        ld_tile_async(sb + AK0, g_kb0 + (size_t)(kofs + kb) * CC, tid);
        ld_tile_async(sb + AK1, g_kb1 + (size_t)(kofs + kb) * CC, tid);
        CP_COMMIT();
        ld_tile_async(sb + AV0, g_vh + (size_t)(kofs + kb) * CC, tid);
        CP_COMMIT();
        CP_WAIT(1);        // K ready; V in flight
        __syncthreads();

        float sc[16][4];
        #pragma unroll
        for (int i = 0; i < 16; i++)
            #pragma unroll
            for (int j = 0; j < 4; j++) sc[i][j] = 0.f;

        // scores: (q0+q1)k0 + q0k1
        #pragma unroll
        for (int kc = 0; kc < 8; kc++) {
            uint32_t a0[4], a1[4];
            ldsm4(a0, sb + AQ0 + aoff + kc * 32);
            ldsm4(a1, sb + AQ1 + aoff + kc * 32);
            #pragma unroll
            for (int nt2 = 0; nt2 < 8; nt2++) {
                uint32_t b[4];
                ldsm4(b, sb + AK0 + (uint32_t)(nt2 * 16 * 272) + boff + kc * 32);
                mma16816(sc[2 * nt2],     a0, b[0], b[1]);
                mma16816(sc[2 * nt2 + 1], a0, b[2], b[3]);
                mma16816(sc[2 * nt2],     a1, b[0], b[1]);
                mma16816(sc[2 * nt2 + 1], a1, b[2], b[3]);
            }
            #pragma unroll
            for (int nt2 = 0; nt2 < 8; nt2++) {
                uint32_t b[4];
                ldsm4(b, sb + AK1 + (uint32_t)(nt2 * 16 * 272) + boff + kc * 32);
                mma16816(sc[2 * nt2],     a0, b[0], b[1]);
                mma16816(sc[2 * nt2 + 1], a0, b[2], b[3]);
            }
        }

        // exp; diag mask only in the one tile containing the diagonal
        float rs0 = 0.f, rs1 = 0.f;
        if (kofs + kb == qbase) {
            #pragma unroll
            for (int nt = 0; nt < 16; nt++) {
                int gc = kofs + kb + nt * 8 + qc;
                float e0 = (gr0 == gc)     ? 0.f : __expf(sc[nt][0]);
                float e1 = (gr0 == gc + 1) ? 0.f : __expf(sc[nt][1]);
                float e2 = (gr1 == gc)     ? 0.f : __expf(sc[nt][2]);
                float e3 = (gr1 == gc + 1) ? 0.f : __expf(sc[nt][3]);
                sc[nt][0] = e0; sc[nt][1] = e1; sc[nt][2] = e2; sc[nt][3] = e3;
                rs0 += e0 + e1; rs1 += e2 + e3;
            }
        } else {
            #pragma unroll
            for (int nt = 0; nt < 16; nt++) {
                float e0 = __expf(sc[nt][0]);
                float e1 = __expf(sc[nt][1]);
                float e2 = __expf(sc[nt][2]);
                float e3 = __expf(sc[nt][3]);
                sc[nt][0] = e0; sc[nt][1] = e1; sc[nt][2] = e2; sc[nt][3] = e3;
                rs0 += e0 + e1; rs1 += e2 + e3;
            }
        }
        rs0 += __shfl_xor_sync(0xffffffffu, rs0, 1);
        rs0 += __shfl_xor_sync(0xffffffffu, rs0, 2);
        rs1 += __shfl_xor_sync(0xffffffffu, rs1, 1);
        rs1 += __shfl_xor_sync(0xffffffffu, rs1, 2);
        l0 += rs0; l1 += rs1;

        CP_WAIT(0);        // V ready
        __syncthreads();

        // PV: fp16, p = p0 + p1 (2 products), single V tile
        #pragma unroll
        for (int kc = 0; kc < 8; kc++) {
            uint32_t p0[4], p1[4];
            split_pair_h(sc[2 * kc][0],     sc[2 * kc][1],     p0[0], p1[0]);
            split_pair_h(sc[2 * kc][2],     sc[2 * kc][3],     p0[1], p1[1]);
            split_pair_h(sc[2 * kc + 1][0], sc[2 * kc + 1][1], p0[2], p1[2]);
            split_pair_h(sc[2 * kc + 1][2], sc[2 * kc + 1][3], p0[3], p1[3]);
            #pragma unroll
            for (int nt2 = 0; nt2 < 8; nt2++) {
                uint32_t vf[4];
                ldsm4t(vf, sb + AV0 + (uint32_t)(kc * 16 * 272) + voff + nt2 * 32);
                mma16816h(pv[2 * nt2],     p0, vf[0], vf[1]);
                mma16816h(pv[2 * nt2 + 1], p0, vf[2], vf[3]);
                mma16816h(pv[2 * nt2],     p1, vf[0], vf[1]);
                mma16816h(pv[2 * nt2 + 1], p1, vf[2], vf[3]);
            }
        }
        __syncthreads();   // PV reads done before next tile's cp.async
    }

    float* aout = g_acc + (size_t)blockIdx.y * NN * CC;
    #pragma unroll
    for (int nt = 0; nt < 16; nt++) {
        int c = nt * 8 + qc;
        *reinterpret_cast<float2*>(aout + (size_t)gr0 * CC + c) = make_float2(pv[nt][0], pv[nt][1]);
        *reinterpret_cast<float2*>(aout + (size_t)gr1 * CC + c) = make_float2(pv[nt][2], pv[nt][3]);
    }
    if ((lane & 3) == 0) {
        g_l[blockIdx.y * NN + gr0] = l0;
        g_l[blockIdx.y * NN + gr1] = l1;
    }
}

// ---------------- K3: fused combine + norm + bf16 split ----------------
__global__ __launch_bounds__(256) void combine_norm_kernel()
{
    int row  = blockIdx.x * 8 + (threadIdx.x >> 5);
    int lane = threadIdx.x & 31;
    size_t base = (size_t)row * CC + lane * 4;

    float inv = __fdividef(1.f, g_l[row] + g_l[NN + row]);
    float4 a0 = *reinterpret_cast<const float4*>(g_acc + base);
    float4 a1 = *reinterpret_cast<const float4*>(g_acc + NN * CC + base);
    float4 sk = *reinterpret_cast<const float4*>(g_skip + base);

    float4 h;
    h.x = (a0.x + a1.x) * inv + sk.x;
    h.y = (a0.y + a1.y) * inv + sk.y;
    h.z = (a0.z + a1.z) * inv + sk.z;
    h.w = (a0.w + a1.w) * inv + sk.w;
    *reinterpret_cast<float4*>(g_h + base) = h;

    uint2 hb = {pack_bf(h.x, h.y), pack_bf(h.z, h.w)};
    *reinterpret_cast<uint2*>(g_hb0 + base) = hb;

    float s = h.x * h.x + h.y * h.y + h.z * h.z + h.w * h.w;
    s += __shfl_xor_sync(0xffffffffu, s, 16);
    s += __shfl_xor_sync(0xffffffffu, s, 8);
    s += __shfl_xor_sync(0xffffffffu, s, 4);
    s += __shfl_xor_sync(0xffffffffu, s, 2);
    s += __shfl_xor_sync(0xffffffffu, s, 1);
    if (lane == 0) g_norm[row] = 0.5f * s;
}

// ---------------- K4: kNN candidates — register top-8 per thread, no score smem ----------------
#define KQ0 0
#define KK0 34816
#define KNR 69632
#define KNN_SMEM 70144

__global__ __launch_bounds__(256, 1) void knn_mma_kernel()
{
    extern __shared__ __align__(16) char smc[];
    const uint32_t sb = smem_u32(smc);
    float* nr_s = reinterpret_cast<float*>(smc + KNR);

    const int tid  = threadIdx.x, wid = tid >> 5, lane = tid & 31;
    const int qbase = blockIdx.x * 128;
    const int kofs  = blockIdx.y * HALFN;

    ld_tile_async(sb + KQ0, g_hb0 + (size_t)qbase * CC, tid);
    CP_COMMIT();

    const int r0   = wid * 16;
    const int qrow = lane >> 2, qc = (lane & 3) * 2;
    const int gr0  = qbase + r0 + qrow, gr1 = gr0 + 8;
    const int lr0  = r0 + qrow, lr1 = lr0 + 8;
    const int slot = lane & 3;

    const uint32_t aoff = (uint32_t)((r0 + (lane & 15)) * 272 + ((lane >> 4) & 1) * 16);
    const uint32_t boff = (uint32_t)(((lane & 7) + ((lane >> 4) & 1) * 8) * 272 + ((lane >> 3) & 1) * 16);

    // per-thread top-8 for each of this thread's 2 rows (pure registers)
    float tv0[8], tv1[8];
    int   ti0[8], ti1[8];
    #pragma unroll
    for (int t = 0; t < 8; t++) { tv0[t] = -3e38f; tv1[t] = -3e38f; ti0[t] = 0; ti1[t] = 0; }
    float vmin0 = -3e38f, vmin1 = -3e38f;

    CP_WAIT(0);
    __syncthreads();

    for (int kb = 0; kb < HALFN; kb += 128) {
        ld_tile_async(sb + KK0, g_hb0 + (size_t)(kofs + kb) * CC, tid);
        CP_COMMIT();
        if (tid < 128) nr_s[tid] = g_norm[kofs + kb + tid];
        CP_WAIT(0);
        __syncthreads();

        float sc[16][4];
        #pragma unroll
        for (int i = 0; i < 16; i++)
            #pragma unroll
            for (int j = 0; j < 4; j++) sc[i][j] = 0.f;

        #pragma unroll
        for (int kc = 0; kc < 8; kc++) {
            uint32_t a[4];
            ldsm4(a, sb + KQ0 + aoff + kc * 32);
            #pragma unroll
            for (int nt2 = 0; nt2 < 8; nt2++) {
                uint32_t b[4];
                ldsm4(b, sb + KK0 + (uint32_t)(nt2 * 16 * 272) + boff + kc * 32);
                mma16816(sc[2 * nt2],     a, b[0], b[1]);
                mma16816(sc[2 * nt2 + 1], a, b[2], b[3]);
            }
        }

        // adjust, mask (uniform branch), register top-8 update
        const bool hasdiag = (kofs + kb == qbase);
        #pragma unroll
        for (int nt = 0; nt < 16; nt++) {
            int c = nt * 8 + qc;
            int gc = kofs + kb + c;
            float nr0 = nr_s[c], nr1 = nr_s[c + 1];
            float v0 = sc[nt][0] - nr0;
            float v1 = sc[nt][1] - nr1;
            float v2 = sc[nt][2] - nr0;
            float v3 = sc[nt][3] - nr1;
            if (hasdiag) {
                if (gr0 == gc)     v0 = -3e38f;
                if (gr0 == gc + 1) v1 = -3e38f;
                if (gr1 == gc)     v2 = -3e38f;
                if (gr1 == gc + 1) v3 = -3e38f;
            }
            if (v0 > vmin0) { ins8(tv0, ti0, v0, gc);     vmin0 = tv0[7]; }
            if (v1 > vmin0) { ins8(tv0, ti0, v1, gc + 1); vmin0 = tv0[7]; }
            if (v2 > vmin1) { ins8(tv1, ti1, v2, gc);     vmin1 = tv1[7]; }
            if (v3 > vmin1) { ins8(tv1, ti1, v3, gc + 1); vmin1 = tv1[7]; }
        }
        __syncthreads();   // MMA reads done before next tile's cp.async
    }

    // merge: 4 threads x 8 entries per row -> smem -> top-16 per row
    float* mv = reinterpret_cast<float*>(smc);            // [128][32]
    int*   mi = reinterpret_cast<int*>(smc + 16384);      // [128][32]
    #pragma unroll
    for (int t = 0; t < 8; t++) {
        mv[lr0 * 32 + slot * 8 + t] = tv0[t];
        mi[lr0 * 32 + slot * 8 + t] = ti0[t];
        mv[lr1 * 32 + slot * 8 + t] = tv1[t];
        mi[lr1 * 32 + slot * 8 + t] = ti1[t];
    }
    __syncthreads();

    if (tid < 128) {
        const float* rv = mv + tid * 32;
        const int*   ri = mi + tid * 32;
        float bv[NCAND]; int bi[NCAND];
        #pragma unroll
        for (int t = 0; t < NCAND; t++) { bv[t] = -3e38f; bi[t] = 0; }
        float vm = -3e38f;
        #pragma unroll 4
        for (int j = 0; j < 32; j++) {
            float v = rv[j];
            if (v > vm) {
                float cv = v; int ci2 = ri[j];
                #pragma unroll
                for (int t = 0; t < NCAND; t++) {
                    if (cv > bv[t]) {
                        float a = bv[t]; bv[t] = cv; cv = a;
                        int   b = bi[t]; bi[t] = ci2; ci2 = b;
                    }
                }
                vm = bv[NCAND - 1];
            }
        }
        float* outv = g_cv16 + (size_t)blockIdx.y * NN * NCAND + (size_t)(qbase + tid) * NCAND;
        int*   outi = g_ci16 + (size_t)blockIdx.y * NN * NCAND + (size_t)(qbase + tid) * NCAND;
        #pragma unroll
        for (int t = 0; t < NCAND; t++) { outv[t] = bv[t]; outi[t] = bi[t]; }
    }
}

// ---------------- K5: exact fp32 rescore of 32 candidates -> top-7 ----------------
__global__ __launch_bounds__(256) void knn_rescore_kernel()
{
    int node = (blockIdx.x * 256 + threadIdx.x) >> 5;
    int lane = threadIdx.x & 31;

    float4 hv = *reinterpret_cast<const float4*>(g_h + (size_t)node * CC + lane * 4);
    int half = lane >> 4, slot = lane & 15;
    int ci = g_ci16[(size_t)half * NN * NCAND + (size_t)node * NCAND + slot];

    float myv = -3e38f;
    for (int c = 0; c < 32; c++) {
        int cj = __shfl_sync(0xffffffffu, ci, c);
        float4 hc = *reinterpret_cast<const float4*>(g_h + (size_t)cj * CC + lane * 4);
        float p = hv.x * hc.x + hv.y * hc.y + hv.z * hc.z + hv.w * hc.w;
        #pragma unroll
        for (int m = 16; m >= 1; m >>= 1) p += __shfl_xor_sync(0xffffffffu, p, m);
        if (lane == c) myv = p - g_norm[cj];
    }

    float v = myv; int idx = ci;
    #pragma unroll
    for (int t = 0; t < KNBR; t++) {
        float bv = v; int bidx = idx;
        #pragma unroll
        for (int m = 16; m >= 1; m >>= 1) {
            float ov = __shfl_xor_sync(0xffffffffu, bv, m);
            int   oi = __shfl_xor_sync(0xffffffffu, bidx, m);
            if (ov > bv || (ov == bv && oi < bidx)) { bv = ov; bidx = oi; }
        }
        if (lane == 0) g_idx[node * KNBR + t] = bidx;
        if (idx == bidx) v = -3.3e38f;
    }
}

// ---------------- K6: m1 = h @ W1 ----------------
__global__ __launch_bounds__(256) void gcn1_gemm(const float* __restrict__ W1)
{
    __shared__ float xs[32 * 129];
    const int tid = threadIdx.x;
    const int r0  = blockIdx.x * 32;

    for (int i = tid; i < 32 * CC; i += 256) {
        int r = i >> 7, c = i & 127;
        xs[r * 129 + c] = g_h[(r0 + r) * CC + c];
    }
    __syncthreads();

    const int ri = (tid >> 5) * 4;
    const int c0 = (tid & 31) * 4;

    ull acc[4][2];
    #pragma unroll
    for (int i = 0; i < 4; i++) { acc[i][0] = 0ULL; acc[i][1] = 0ULL; }

    #pragma unroll 4
    for (int k2 = 0; k2 < CC; k2++) {
        ulonglong2 wp = *reinterpret_cast<const ulonglong2*>(W1 + k2 * CC + c0);
        #pragma unroll
        for (int dr = 0; dr < 4; dr++) {
            ull x2 = dup2(xs[(ri + dr) * 129 + k2]);
            acc[dr][0] = ffma2(x2, wp.x, acc[dr][0]);
            acc[dr][1] = ffma2(x2, wp.y, acc[dr][1]);
        }
    }
    #pragma unroll
    for (int dr = 0; dr < 4; dr++) {
        float2 a0 = upk(acc[dr][0]), a1 = upk(acc[dr][1]);
        float4 o = {a0.x, a0.y, a1.x, a1.y};
        *reinterpret_cast<float4*>(g_m1 + (r0 + ri + dr) * CC + c0) = o;
    }
}

// ---------------- K7: GCN layer-1 gather + relu ----------------
__global__ __launch_bounds__(128) void gather1(const float* __restrict__ b1)
{
    int node = blockIdx.x;
    int c    = threadIdx.x;
    float s = g_m1[node * CC + c];
    #pragma unroll
    for (int t = 0; t < KNBR; t++) {
        int nb = g_idx[node * KNBR + t];
        s += g_m1[nb * CC + c];
    }
    g_h1[node * CC + c] = fmaxf(s * 0.125f + b1[c], 0.f);
}

// ---------------- K8: m2 = h1 @ W2 ----------------
__global__ __launch_bounds__(256) void m2_kernel(const float* __restrict__ W2)
{
    int row  = blockIdx.x * 8 + (threadIdx.x >> 5);
    int lane = threadIdx.x & 31;
    float s = 0.f;
    for (int c = lane; c < CC; c += 32) s += g_h1[row * CC + c] * W2[c];
    s += __shfl_xor_sync(0xffffffffu, s, 16);
    s += __shfl_xor_sync(0xffffffffu, s, 8);
    s += __shfl_xor_sync(0xffffffffu, s, 4);
    s += __shfl_xor_sync(0xffffffffu, s, 2);
    s += __shfl_xor_sync(0xffffffffu, s, 1);
    if (lane == 0) g_m2[row] = s;
}

// ---------------- K9: GCN layer-2 gather -> output ----------------
__global__ __launch_bounds__(256) void out_kernel(const float* __restrict__ b2,
                                                  float* __restrict__ out)
{
    int n = blockIdx.x * 256 + threadIdx.x;
    float s = g_m2[n];
    #pragma unroll
    for (int t = 0; t < KNBR; t++) s += g_m2[g_idx[n * KNBR + t]];
    out[n] = s * 0.125f + b2[0];
}

// ---------------- launch ----------------
extern "C" void kernel_launch(void* const* d_in, const int* in_sizes, int n_in,
                              void* d_out, int out_size)
{
    const float* x   = (const float*)d_in[0];
    const float* Wq  = (const float*)d_in[1];
    const float* bq  = (const float*)d_in[2];
    const float* Wk  = (const float*)d_in[3];
    const float* bk  = (const float*)d_in[4];
    const float* Wv  = (const float*)d_in[5];
    const float* bv  = (const float*)d_in[6];
    const float* Wsk = (const float*)d_in[7];
    const float* bsk = (const float*)d_in[8];
    const float* W1  = (const float*)d_in[9];
    const float* b1  = (const float*)d_in[10];
    const float* W2  = (const float*)d_in[11];
    const float* b2  = (const float*)d_in[12];
    float* out = (float*)d_out;

    cudaFuncSetAttribute(attn_mma_kernel, cudaFuncAttributeMaxDynamicSharedMemorySize, ATTN_SMEM);
    cudaFuncSetAttribute(knn_mma_kernel,  cudaFuncAttributeMaxDynamicSharedMemorySize, KNN_SMEM);

    proj_kernel<<<NN / 32, 256>>>(x, Wq, bq, Wk, bk, Wv, bv, Wsk, bsk);
    attn_mma_kernel<<<dim3(NN / 128, 2), 256, ATTN_SMEM>>>();
    combine_norm_kernel<<<NN / 8, 256>>>();
    knn_mma_kernel<<<dim3(NN / 128, 2), 256, KNN_SMEM>>>();
    knn_rescore_kernel<<<NN / 8, 256>>>();
    gcn1_gemm<<<NN / 32, 256>>>(W1);
    gather1<<<NN, CC>>>(b1);
    m2_kernel<<<NN / 8, 256>>>(W2);
    out_kernel<<<NN / 256, 256>>>(b2, out);
}

// round 8
// speedup vs baseline: 4.9866x; 1.0045x over previous
#include <cuda_runtime.h>
#include <cuda_bf16.h>
#include <cuda_fp16.h>
#include <cstdint>

#define NN    8192
#define CC    128
#define KNBR  7
#define HALFN 4096
#define NCAND 16
#define NT    (HALFN / 128)

typedef unsigned long long ull;

// ---------------- device scratch ----------------
__device__ float g_skip[NN * CC];
__device__ float g_h[NN * CC];
__device__ float g_acc[2 * NN * CC];
__device__ float g_l[2 * NN];
__device__ float g_norm[NN];
__device__ float g_cv16[2 * NN * NCAND];
__device__ int   g_ci16[2 * NN * NCAND];
__device__ int   g_idx[NN * KNBR];
__device__ float g_m1[NN * CC];
__device__ float g_h1[NN * CC];
__device__ float g_m2[NN];
__device__ __nv_bfloat16 g_qb0[NN * CC], g_qb1[NN * CC];
__device__ __nv_bfloat16 g_kb0[NN * CC], g_kb1[NN * CC];
__device__ __half        g_vh[NN * CC];
__device__ __nv_bfloat16 g_hb0[NN * CC];

// ---------------- packed fp32x2 (SIMT GEMMs) ----------------
__device__ __forceinline__ ull ffma2(ull a, ull b, ull c) {
    ull d;
    asm("fma.rn.f32x2 %0, %1, %2, %3;" : "=l"(d) : "l"(a), "l"(b), "l"(c));
    return d;
}
__device__ __forceinline__ ull dup2(float x) {
    ull d;
    asm("mov.b64 %0, {%1, %1};" : "=l"(d) : "f"(x));
    return d;
}
__device__ __forceinline__ float2 upk(ull v) {
    float2 r;
    asm("mov.b64 {%0, %1}, %2;" : "=f"(r.x), "=f"(r.y) : "l"(v));
    return r;
}

// ---------------- mma / ldmatrix / cp.async helpers ----------------
__device__ __forceinline__ uint32_t smem_u32(const void* p) {
    uint32_t a;
    asm("{ .reg .u64 t; cvta.to.shared.u64 t, %1; cvt.u32.u64 %0, t; }" : "=r"(a) : "l"(p));
    return a;
}
__device__ __forceinline__ void ldsm4(uint32_t* r, uint32_t a) {
    asm volatile("ldmatrix.sync.aligned.m8n8.x4.shared.b16 {%0,%1,%2,%3}, [%4];"
                 : "=r"(r[0]), "=r"(r[1]), "=r"(r[2]), "=r"(r[3]) : "r"(a));
}
__device__ __forceinline__ void ldsm4t(uint32_t* r, uint32_t a) {
    asm volatile("ldmatrix.sync.aligned.m8n8.x4.trans.shared.b16 {%0,%1,%2,%3}, [%4];"
                 : "=r"(r[0]), "=r"(r[1]), "=r"(r[2]), "=r"(r[3]) : "r"(a));
}
__device__ __forceinline__ void mma16816(float* c, const uint32_t* a, uint32_t b0, uint32_t b1) {
    asm volatile(
        "mma.sync.aligned.m16n8k16.row.col.f32.bf16.bf16.f32 "
        "{%0,%1,%2,%3}, {%4,%5,%6,%7}, {%8,%9}, {%0,%1,%2,%3};"
        : "+f"(c[0]), "+f"(c[1]), "+f"(c[2]), "+f"(c[3])
        : "r"(a[0]), "r"(a[1]), "r"(a[2]), "r"(a[3]), "r"(b0), "r"(b1));
}
__device__ __forceinline__ void mma16816h(float* c, const uint32_t* a, uint32_t b0, uint32_t b1) {
    asm volatile(
        "mma.sync.aligned.m16n8k16.row.col.f32.f16.f16.f32 "
        "{%0,%1,%2,%3}, {%4,%5,%6,%7}, {%8,%9}, {%0,%1,%2,%3};"
        : "+f"(c[0]), "+f"(c[1]), "+f"(c[2]), "+f"(c[3])
        : "r"(a[0]), "r"(a[1]), "r"(a[2]), "r"(a[3]), "r"(b0), "r"(b1));
}
#define CP_COMMIT() asm volatile("cp.async.commit_group;" ::: "memory")
#define CP_WAIT(n)  asm volatile("cp.async.wait_group %0;" :: "n"(n) : "memory")

__device__ __forceinline__ uint32_t pack_bf(float x, float y) {
    __nv_bfloat162 t = __floats2bfloat162_rn(x, y);
    return *reinterpret_cast<uint32_t*>(&t);
}
__device__ __forceinline__ uint32_t pack_h(float x, float y) {
    __half2 t = __floats2half2_rn(x, y);
    return *reinterpret_cast<uint32_t*>(&t);
}
__device__ __forceinline__ void split_pair(float x, float y, uint32_t& p0, uint32_t& p1) {
    __nv_bfloat16 bx = __float2bfloat16_rn(x), by = __float2bfloat16_rn(y);
    __nv_bfloat162 t; t.x = bx; t.y = by;
    p0 = *reinterpret_cast<uint32_t*>(&t);
    p1 = pack_bf(x - __bfloat162float(bx), y - __bfloat162float(by));
}
__device__ __forceinline__ void split_pair_h(float x, float y, uint32_t& p0, uint32_t& p1) {
    __half hx = __float2half_rn(x), hy = __float2half_rn(y);
    __half2 t; t.x = hx; t.y = hy;
    p0 = *reinterpret_cast<uint32_t*>(&t);
    p1 = pack_h(x - __half2float(hx), y - __half2float(hy));
}
// async 128x128 16-bit tile -> smem rows of 272B
__device__ __forceinline__ void ld_tile_async(uint32_t dst, const void* __restrict__ srcv, int tid) {
    const char* src = reinterpret_cast<const char*>(srcv);
    #pragma unroll
    for (int i = 0; i < 8; i++) {
        int idx = tid + i * 256;
        int row = idx >> 4, ch = idx & 15;
        asm volatile("cp.async.cg.shared.global [%0], [%1], 16;" ::
            "r"(dst + (uint32_t)(row * 272 + ch * 16)), "l"(src + (size_t)row * CC * 2 + ch * 16) : "memory");
    }
}
// register top-8 insert (precondition: v beats tv[7])
__device__ __forceinline__ void ins8(float* tv, int* ti, float v, int idx) {
    #pragma unroll
    for (int t = 0; t < 8; t++) {
        if (v > tv[t]) {
            float a = tv[t]; tv[t] = v; v = a;
            int   b = ti[t]; ti[t] = idx; idx = b;
        }
    }
}

// ---------------- K1: fused projections -> bf16 splits (q,k), fp16 (v), skip ----------------
__global__ __launch_bounds__(256) void proj_kernel(
    const float* __restrict__ x,
    const float* __restrict__ Wq, const float* __restrict__ bq,
    const float* __restrict__ Wk, const float* __restrict__ bk,
    const float* __restrict__ Wv, const float* __restrict__ bv,
    const float* __restrict__ Ws, const float* __restrict__ bs)
{
    __shared__ float xs[32 * 129];
    const int tid = threadIdx.x;
    const int r0  = blockIdx.x * 32;
    const float SCALE = 0.08838834764831843f;

    for (int i = tid; i < 32 * CC; i += 256) {
        int r = i >> 7, c = i & 127;
        xs[r * 129 + c] = x[(r0 + r) * CC + c];
    }
    __syncthreads();

    const int ri = (tid >> 5) * 4;
    const int c0 = (tid & 31) * 4;

    const float* Wt[4] = {Wq, Wk, Wv, Ws};
    const float* bt[4] = {bq, bk, bv, bs};

    #pragma unroll
    for (int w = 0; w < 4; w++) {
        const float* W = Wt[w];
        ull acc[4][2];
        #pragma unroll
        for (int i = 0; i < 4; i++) { acc[i][0] = 0ULL; acc[i][1] = 0ULL; }

        #pragma unroll 4
        for (int k2 = 0; k2 < CC; k2++) {
            ulonglong2 wp = *reinterpret_cast<const ulonglong2*>(W + k2 * CC + c0);
            #pragma unroll
            for (int dr = 0; dr < 4; dr++) {
                ull x2 = dup2(xs[(ri + dr) * 129 + k2]);
                acc[dr][0] = ffma2(x2, wp.x, acc[dr][0]);
                acc[dr][1] = ffma2(x2, wp.y, acc[dr][1]);
            }
        }
        float4 bb = *reinterpret_cast<const float4*>(bt[w] + c0);
        #pragma unroll
        for (int dr = 0; dr < 4; dr++) {
            float2 a0 = upk(acc[dr][0]), a1 = upk(acc[dr][1]);
            int row = r0 + ri + dr;
            float ox = a0.x + bb.x, oy = a0.y + bb.y;
            float oz = a1.x + bb.z, ow = a1.y + bb.w;
            if (w == 3) {
                float4 o = {ox, oy, oz, ow};
                *reinterpret_cast<float4*>(g_skip + row * CC + c0) = o;
            } else if (w == 2) {
                uint2 u = {pack_h(ox, oy), pack_h(oz, ow)};
                *reinterpret_cast<uint2*>(g_vh + row * CC + c0) = u;
            } else {
                float s = (w == 0) ? SCALE : 1.f;
                ox *= s; oy *= s; oz *= s; ow *= s;
                uint32_t lo0, hi0, lo1, hi1;
                split_pair(ox, oy, lo0, hi0);
                split_pair(oz, ow, lo1, hi1);
                __nv_bfloat16* d0 = (w == 0) ? g_qb0 : g_kb0;
                __nv_bfloat16* d1 = (w == 0) ? g_qb1 : g_kb1;
                uint2 u0 = {lo0, lo1};
                uint2 u1 = {hi0, hi1};
                *reinterpret_cast<uint2*>(d0 + row * CC + c0) = u0;
                *reinterpret_cast<uint2*>(d1 + row * CC + c0) = u1;
            }
        }
    }
}

// ---------------- K2: flash attention, pipelined (K load under PV, V load under scores) ----------------
#define AQ0 0
#define AQ1 34816
#define AK0 69632
#define AK1 104448
#define AV0 139264
#define ATTN_SMEM 174080

__global__ __launch_bounds__(256, 1) void attn_mma_kernel()
{
    extern __shared__ __align__(16) char smc[];
    const uint32_t sb = smem_u32(smc);
    const int tid  = threadIdx.x, wid = tid >> 5, lane = tid & 31;
    const int qbase = blockIdx.x * 128;
    const int kofs  = blockIdx.y * HALFN;

    // prologue: Q group, K(0) group, V(0) group
    ld_tile_async(sb + AQ0, g_qb0 + (size_t)qbase * CC, tid);
    ld_tile_async(sb + AQ1, g_qb1 + (size_t)qbase * CC, tid);
    CP_COMMIT();
    ld_tile_async(sb + AK0, g_kb0 + (size_t)kofs * CC, tid);
    ld_tile_async(sb + AK1, g_kb1 + (size_t)kofs * CC, tid);
    CP_COMMIT();
    ld_tile_async(sb + AV0, g_vh + (size_t)kofs * CC, tid);
    CP_COMMIT();

    const int r0   = wid * 16;
    const int qrow = lane >> 2, qc = (lane & 3) * 2;
    const int gr0  = qbase + r0 + qrow, gr1 = gr0 + 8;

    const uint32_t aoff = (uint32_t)((r0 + (lane & 15)) * 272 + ((lane >> 4) & 1) * 16);
    const uint32_t boff = (uint32_t)(((lane & 7) + ((lane >> 4) & 1) * 8) * 272 + ((lane >> 3) & 1) * 16);
    const uint32_t voff = (uint32_t)(((lane & 7) + ((lane >> 3) & 1) * 8) * 272 + ((lane >> 4) & 1) * 16);

    float pv[16][4];
    #pragma unroll
    for (int i = 0; i < 16; i++)
        #pragma unroll
        for (int j = 0; j < 4; j++) pv[i][j] = 0.f;
    float l0 = 0.f, l1 = 0.f;

    CP_WAIT(1);        // Q + K(0) done; V(0) may be in flight
    __syncthreads();

    for (int t = 0; t < NT; t++) {
        const int kb = t * 128;
        const bool more = (t + 1 < NT);

        float sc[16][4];
        #pragma unroll
        for (int i = 0; i < 16; i++)
            #pragma unroll
            for (int j = 0; j < 4; j++) sc[i][j] = 0.f;

        // scores: (q0+q1)k0 + q0k1
        #pragma unroll
        for (int kc = 0; kc < 8; kc++) {
            uint32_t a0[4], a1[4];
            ldsm4(a0, sb + AQ0 + aoff + kc * 32);
            ldsm4(a1, sb + AQ1 + aoff + kc * 32);
            #pragma unroll
            for (int nt2 = 0; nt2 < 8; nt2++) {
                uint32_t b[4];
                ldsm4(b, sb + AK0 + (uint32_t)(nt2 * 16 * 272) + boff + kc * 32);
                mma16816(sc[2 * nt2],     a0, b[0], b[1]);
                mma16816(sc[2 * nt2 + 1], a0, b[2], b[3]);
                mma16816(sc[2 * nt2],     a1, b[0], b[1]);
                mma16816(sc[2 * nt2 + 1], a1, b[2], b[3]);
            }
            #pragma unroll
            for (int nt2 = 0; nt2 < 8; nt2++) {
                uint32_t b[4];
                ldsm4(b, sb + AK1 + (uint32_t)(nt2 * 16 * 272) + boff + kc * 32);
                mma16816(sc[2 * nt2],     a0, b[0], b[1]);
                mma16816(sc[2 * nt2 + 1], a0, b[2], b[3]);
            }
        }

        // exp; diag mask only in the tile containing the diagonal
        float rs0 = 0.f, rs1 = 0.f;
        if (kofs + kb == qbase) {
            #pragma unroll
            for (int nt = 0; nt < 16; nt++) {
                int gc = kofs + kb + nt * 8 + qc;
                float e0 = (gr0 == gc)     ? 0.f : __expf(sc[nt][0]);
                float e1 = (gr0 == gc + 1) ? 0.f : __expf(sc[nt][1]);
                float e2 = (gr1 == gc)     ? 0.f : __expf(sc[nt][2]);
                float e3 = (gr1 == gc + 1) ? 0.f : __expf(sc[nt][3]);
                sc[nt][0] = e0; sc[nt][1] = e1; sc[nt][2] = e2; sc[nt][3] = e3;
                rs0 += e0 + e1; rs1 += e2 + e3;
            }
        } else {
            #pragma unroll
            for (int nt = 0; nt < 16; nt++) {
                float e0 = __expf(sc[nt][0]);
                float e1 = __expf(sc[nt][1]);
                float e2 = __expf(sc[nt][2]);
                float e3 = __expf(sc[nt][3]);
                sc[nt][0] = e0; sc[nt][1] = e1; sc[nt][2] = e2; sc[nt][3] = e3;
                rs0 += e0 + e1; rs1 += e2 + e3;
            }
        }
        rs0 += __shfl_xor_sync(0xffffffffu, rs0, 1);
        rs0 += __shfl_xor_sync(0xffffffffu, rs0, 2);
        rs1 += __shfl_xor_sync(0xffffffffu, rs1, 1);
        rs1 += __shfl_xor_sync(0xffffffffu, rs1, 2);
        l0 += rs0; l1 += rs1;

        CP_WAIT(0);        // V(t) done
        __syncthreads();   // V visible; all warps done reading K

        if (more) {        // K(t+1) load overlaps the PV phase
            ld_tile_async(sb + AK0, g_kb0 + (size_t)(kofs + kb + 128) * CC, tid);
            ld_tile_async(sb + AK1, g_kb1 + (size_t)(kofs + kb + 128) * CC, tid);
            CP_COMMIT();
        }

        // PV: fp16, p = p0 + p1 (2 products), single V tile
        #pragma unroll
        for (int kc = 0; kc < 8; kc++) {
            uint32_t p0[4], p1[4];
            split_pair_h(sc[2 * kc][0],     sc[2 * kc][1],     p0[0], p1[0]);
            split_pair_h(sc[2 * kc][2],     sc[2 * kc][3],     p0[1], p1[1]);
            split_pair_h(sc[2 * kc + 1][0], sc[2 * kc + 1][1], p0[2], p1[2]);
            split_pair_h(sc[2 * kc + 1][2], sc[2 * kc + 1][3], p0[3], p1[3]);
            #pragma unroll
            for (int nt2 = 0; nt2 < 8; nt2++) {
                uint32_t vf[4];
                ldsm4t(vf, sb + AV0 + (uint32_t)(kc * 16 * 272) + voff + nt2 * 32);
                mma16816h(pv[2 * nt2],     p0, vf[0], vf[1]);
                mma16816h(pv[2 * nt2 + 1], p0, vf[2], vf[3]);
                mma16816h(pv[2 * nt2],     p1, vf[0], vf[1]);
                mma16816h(pv[2 * nt2 + 1], p1, vf[2], vf[3]);
            }
        }
        __syncthreads();   // V reads done

        if (more) {        // V(t+1) overlaps next score phase
            ld_tile_async(sb + AV0, g_vh + (size_t)(kofs + kb + 128) * CC, tid);
            CP_COMMIT();
            CP_WAIT(1);    // K(t+1) done; V(t+1) in flight
            __syncthreads();
        }
    }

    float* aout = g_acc + (size_t)blockIdx.y * NN * CC;
    #pragma unroll
    for (int nt = 0; nt < 16; nt++) {
        int c = nt * 8 + qc;
        *reinterpret_cast<float2*>(aout + (size_t)gr0 * CC + c) = make_float2(pv[nt][0], pv[nt][1]);
        *reinterpret_cast<float2*>(aout + (size_t)gr1 * CC + c) = make_float2(pv[nt][2], pv[nt][3]);
    }
    if ((lane & 3) == 0) {
        g_l[blockIdx.y * NN + gr0] = l0;
        g_l[blockIdx.y * NN + gr1] = l1;
    }
}

// ---------------- K3: fused combine + norm + bf16 split ----------------
__global__ __launch_bounds__(256) void combine_norm_kernel()
{
    int row  = blockIdx.x * 8 + (threadIdx.x >> 5);
    int lane = threadIdx.x & 31;
    size_t base = (size_t)row * CC + lane * 4;

    float inv = __fdividef(1.f, g_l[row] + g_l[NN + row]);
    float4 a0 = *reinterpret_cast<const float4*>(g_acc + base);
    float4 a1 = *reinterpret_cast<const float4*>(g_acc + NN * CC + base);
    float4 sk = *reinterpret_cast<const float4*>(g_skip + base);

    float4 h;
    h.x = (a0.x + a1.x) * inv + sk.x;
    h.y = (a0.y + a1.y) * inv + sk.y;
    h.z = (a0.z + a1.z) * inv + sk.z;
    h.w = (a0.w + a1.w) * inv + sk.w;
    *reinterpret_cast<float4*>(g_h + base) = h;

    uint2 hb = {pack_bf(h.x, h.y), pack_bf(h.z, h.w)};
    *reinterpret_cast<uint2*>(g_hb0 + base) = hb;

    float s = h.x * h.x + h.y * h.y + h.z * h.z + h.w * h.w;
    s += __shfl_xor_sync(0xffffffffu, s, 16);
    s += __shfl_xor_sync(0xffffffffu, s, 8);
    s += __shfl_xor_sync(0xffffffffu, s, 4);
    s += __shfl_xor_sync(0xffffffffu, s, 2);
    s += __shfl_xor_sync(0xffffffffu, s, 1);
    if (lane == 0) g_norm[row] = 0.5f * s;
}

// ---------------- K4: kNN candidates — double-buffered K tiles, register top-8 ----------------
#define KQ0 0
#define KKA 34816
#define KKB 69632
#define KNR 104448         // 2 x 128 f32
#define KNN_SMEM 105472

__global__ __launch_bounds__(256, 1) void knn_mma_kernel()
{
    extern __shared__ __align__(16) char smc[];
    const uint32_t sb = smem_u32(smc);
    float* nr_all = reinterpret_cast<float*>(smc + KNR);

    const int tid  = threadIdx.x, wid = tid >> 5, lane = tid & 31;
    const int qbase = blockIdx.x * 128;
    const int kofs  = blockIdx.y * HALFN;

    // prologue: Q group, K(0) group
    ld_tile_async(sb + KQ0, g_hb0 + (size_t)qbase * CC, tid);
    CP_COMMIT();
    ld_tile_async(sb + KKA, g_hb0 + (size_t)kofs * CC, tid);
    CP_COMMIT();
    if (tid < 128) nr_all[tid] = g_norm[kofs + tid];

    const int r0   = wid * 16;
    const int qrow = lane >> 2, qc = (lane & 3) * 2;
    const int gr0  = qbase + r0 + qrow, gr1 = gr0 + 8;
    const int lr0  = r0 + qrow, lr1 = lr0 + 8;
    const int slot = lane & 3;

    const uint32_t aoff = (uint32_t)((r0 + (lane & 15)) * 272 + ((lane >> 4) & 1) * 16);
    const uint32_t boff = (uint32_t)(((lane & 7) + ((lane >> 4) & 1) * 8) * 272 + ((lane >> 3) & 1) * 16);

    float tv0[8], tv1[8];
    int   ti0[8], ti1[8];
    #pragma unroll
    for (int t = 0; t < 8; t++) { tv0[t] = -3e38f; tv1[t] = -3e38f; ti0[t] = 0; ti1[t] = 0; }
    float vmin0 = -3e38f, vmin1 = -3e38f;

    int buf = 0;
    for (int t = 0; t < NT; t++) {
        // issue next tile into the spare buffer, then wait for current
        if (t + 1 < NT) {
            ld_tile_async(sb + KKA + (uint32_t)((buf ^ 1) * 34816),
                          g_hb0 + (size_t)(kofs + (t + 1) * 128) * CC, tid);
            CP_COMMIT();
            if (tid < 128) nr_all[(buf ^ 1) * 128 + tid] = g_norm[kofs + (t + 1) * 128 + tid];
            CP_WAIT(1);
        } else {
            CP_WAIT(0);
        }
        __syncthreads();   // tile t visible everywhere

        const uint32_t kbase = sb + KKA + (uint32_t)(buf * 34816);
        const float* nr_s = nr_all + buf * 128;

        float sc[16][4];
        #pragma unroll
        for (int i = 0; i < 16; i++)
            #pragma unroll
            for (int j = 0; j < 4; j++) sc[i][j] = 0.f;

        #pragma unroll
        for (int kc = 0; kc < 8; kc++) {
            uint32_t a[4];
            ldsm4(a, sb + KQ0 + aoff + kc * 32);
            #pragma unroll
            for (int nt2 = 0; nt2 < 8; nt2++) {
                uint32_t b[4];
                ldsm4(b, kbase + (uint32_t)(nt2 * 16 * 272) + boff + kc * 32);
                mma16816(sc[2 * nt2],     a, b[0], b[1]);
                mma16816(sc[2 * nt2 + 1], a, b[2], b[3]);
            }
        }

        const int kb = t * 128;
        const bool hasdiag = (kofs + kb == qbase);
        #pragma unroll
        for (int nt = 0; nt < 16; nt++) {
            int c = nt * 8 + qc;
            int gc = kofs + kb + c;
            float nr0 = nr_s[c], nr1 = nr_s[c + 1];
            float v0 = sc[nt][0] - nr0;
            float v1 = sc[nt][1] - nr1;
            float v2 = sc[nt][2] - nr0;
            float v3 = sc[nt][3] - nr1;
            if (hasdiag) {
                if (gr0 == gc)     v0 = -3e38f;
                if (gr0 == gc + 1) v1 = -3e38f;
                if (gr1 == gc)     v2 = -3e38f;
                if (gr1 == gc + 1) v3 = -3e38f;
            }
            if (v0 > vmin0) { ins8(tv0, ti0, v0, gc);     vmin0 = tv0[7]; }
            if (v1 > vmin0) { ins8(tv0, ti0, v1, gc + 1); vmin0 = tv0[7]; }
            if (v2 > vmin1) { ins8(tv1, ti1, v2, gc);     vmin1 = tv1[7]; }
            if (v3 > vmin1) { ins8(tv1, ti1, v3, gc + 1); vmin1 = tv1[7]; }
        }
        __syncthreads();   // ldsm reads of buf done before its next overwrite
        buf ^= 1;
    }

    // merge: 4 threads x 8 entries per row -> smem -> top-16 per row
    float* mv = reinterpret_cast<float*>(smc);            // [128][32]
    int*   mi = reinterpret_cast<int*>(smc + 16384);      // [128][32]
    #pragma unroll
    for (int t = 0; t < 8; t++) {
        mv[lr0 * 32 + slot * 8 + t] = tv0[t];
        mi[lr0 * 32 + slot * 8 + t] = ti0[t];
        mv[lr1 * 32 + slot * 8 + t] = tv1[t];
        mi[lr1 * 32 + slot * 8 + t] = ti1[t];
    }
    __syncthreads();

    if (tid < 128) {
        const float* rv = mv + tid * 32;
        const int*   ri = mi + tid * 32;
        float bv[NCAND]; int bi[NCAND];
        #pragma unroll
        for (int t = 0; t < NCAND; t++) { bv[t] = -3e38f; bi[t] = 0; }
        float vm = -3e38f;
        #pragma unroll 4
        for (int j = 0; j < 32; j++) {
            float v = rv[j];
            if (v > vm) {
                float cv = v; int ci2 = ri[j];
                #pragma unroll
                for (int t = 0; t < NCAND; t++) {
                    if (cv > bv[t]) {
                        float a = bv[t]; bv[t] = cv; cv = a;
                        int   b = bi[t]; bi[t] = ci2; ci2 = b;
                    }
                }
                vm = bv[NCAND - 1];
            }
        }
        float* outv = g_cv16 + (size_t)blockIdx.y * NN * NCAND + (size_t)(qbase + tid) * NCAND;
        int*   outi = g_ci16 + (size_t)blockIdx.y * NN * NCAND + (size_t)(qbase + tid) * NCAND;
        #pragma unroll
        for (int t = 0; t < NCAND; t++) { outv[t] = bv[t]; outi[t] = bi[t]; }
    }
}

// ---------------- K5: exact fp32 rescore of 32 candidates -> top-7 ----------------
__global__ __launch_bounds__(256) void knn_rescore_kernel()
{
    int node = (blockIdx.x * 256 + threadIdx.x) >> 5;
    int lane = threadIdx.x & 31;

    float4 hv = *reinterpret_cast<const float4*>(g_h + (size_t)node * CC + lane * 4);
    int half = lane >> 4, slot = lane & 15;
    int ci = g_ci16[(size_t)half * NN * NCAND + (size_t)node * NCAND + slot];

    float myv = -3e38f;
    for (int c = 0; c < 32; c++) {
        int cj = __shfl_sync(0xffffffffu, ci, c);
        float4 hc = *reinterpret_cast<const float4*>(g_h + (size_t)cj * CC + lane * 4);
        float p = hv.x * hc.x + hv.y * hc.y + hv.z * hc.z + hv.w * hc.w;
        #pragma unroll
        for (int m = 16; m >= 1; m >>= 1) p += __shfl_xor_sync(0xffffffffu, p, m);
        if (lane == c) myv = p - g_norm[cj];
    }

    float v = myv; int idx = ci;
    #pragma unroll
    for (int t = 0; t < KNBR; t++) {
        float bv = v; int bidx = idx;
        #pragma unroll
        for (int m = 16; m >= 1; m >>= 1) {
            float ov = __shfl_xor_sync(0xffffffffu, bv, m);
            int   oi = __shfl_xor_sync(0xffffffffu, bidx, m);
            if (ov > bv || (ov == bv && oi < bidx)) { bv = ov; bidx = oi; }
        }
        if (lane == 0) g_idx[node * KNBR + t] = bidx;
        if (idx == bidx) v = -3.3e38f;
    }
}

// ---------------- K6: m1 = h @ W1 ----------------
__global__ __launch_bounds__(256) void gcn1_gemm(const float* __restrict__ W1)
{
    __shared__ float xs[32 * 129];
    const int tid = threadIdx.x;
    const int r0  = blockIdx.x * 32;

    for (int i = tid; i < 32 * CC; i += 256) {
        int r = i >> 7, c = i & 127;
        xs[r * 129 + c] = g_h[(r0 + r) * CC + c];
    }
    __syncthreads();

    const int ri = (tid >> 5) * 4;
    const int c0 = (tid & 31) * 4;

    ull acc[4][2];
    #pragma unroll
    for (int i = 0; i < 4; i++) { acc[i][0] = 0ULL; acc[i][1] = 0ULL; }

    #pragma unroll 4
    for (int k2 = 0; k2 < CC; k2++) {
        ulonglong2 wp = *reinterpret_cast<const ulonglong2*>(W1 + k2 * CC + c0);
        #pragma unroll
        for (int dr = 0; dr < 4; dr++) {
            ull x2 = dup2(xs[(ri + dr) * 129 + k2]);
            acc[dr][0] = ffma2(x2, wp.x, acc[dr][0]);
            acc[dr][1] = ffma2(x2, wp.y, acc[dr][1]);
        }
    }
    #pragma unroll
    for (int dr = 0; dr < 4; dr++) {
        float2 a0 = upk(acc[dr][0]), a1 = upk(acc[dr][1]);
        float4 o = {a0.x, a0.y, a1.x, a1.y};
        *reinterpret_cast<float4*>(g_m1 + (r0 + ri + dr) * CC + c0) = o;
    }
}

// ---------------- K7: GCN layer-1 gather + relu ----------------
__global__ __launch_bounds__(128) void gather1(const float* __restrict__ b1)
{
    int node = blockIdx.x;
    int c    = threadIdx.x;
    float s = g_m1[node * CC + c];
    #pragma unroll
    for (int t = 0; t < KNBR; t++) {
        int nb = g_idx[node * KNBR + t];
        s += g_m1[nb * CC + c];
    }
    g_h1[node * CC + c] = fmaxf(s * 0.125f + b1[c], 0.f);
}

// ---------------- K8: m2 = h1 @ W2 ----------------
__global__ __launch_bounds__(256) void m2_kernel(const float* __restrict__ W2)
{
    int row  = blockIdx.x * 8 + (threadIdx.x >> 5);
    int lane = threadIdx.x & 31;
    float s = 0.f;
    for (int c = lane; c < CC; c += 32) s += g_h1[row * CC + c] * W2[c];
    s += __shfl_xor_sync(0xffffffffu, s, 16);
    s += __shfl_xor_sync(0xffffffffu, s, 8);
    s += __shfl_xor_sync(0xffffffffu, s, 4);
    s += __shfl_xor_sync(0xffffffffu, s, 2);
    s += __shfl_xor_sync(0xffffffffu, s, 1);
    if (lane == 0) g_m2[row] = s;
}

// ---------------- K9: GCN layer-2 gather -> output ----------------
__global__ __launch_bounds__(256) void out_kernel(const float* __restrict__ b2,
                                                  float* __restrict__ out)
{
    int n = blockIdx.x * 256 + threadIdx.x;
    float s = g_m2[n];
    #pragma unroll
    for (int t = 0; t < KNBR; t++) s += g_m2[g_idx[n * KNBR + t]];
    out[n] = s * 0.125f + b2[0];
}

// ---------------- launch ----------------
extern "C" void kernel_launch(void* const* d_in, const int* in_sizes, int n_in,
                              void* d_out, int out_size)
{
    const float* x   = (const float*)d_in[0];
    const float* Wq  = (const float*)d_in[1];
    const float* bq  = (const float*)d_in[2];
    const float* Wk  = (const float*)d_in[3];
    const float* bk  = (const float*)d_in[4];
    const float* Wv  = (const float*)d_in[5];
    const float* bv  = (const float*)d_in[6];
    const float* Wsk = (const float*)d_in[7];
    const float* bsk = (const float*)d_in[8];
    const float* W1  = (const float*)d_in[9];
    const float* b1  = (const float*)d_in[10];
    const float* W2  = (const float*)d_in[11];
    const float* b2  = (const float*)d_in[12];
    float* out = (float*)d_out;

    cudaFuncSetAttribute(attn_mma_kernel, cudaFuncAttributeMaxDynamicSharedMemorySize, ATTN_SMEM);
    cudaFuncSetAttribute(knn_mma_kernel,  cudaFuncAttributeMaxDynamicSharedMemorySize, KNN_SMEM);

    proj_kernel<<<NN / 32, 256>>>(x, Wq, bq, Wk, bk, Wv, bv, Wsk, bsk);
    attn_mma_kernel<<<dim3(NN / 128, 2), 256, ATTN_SMEM>>>();
    combine_norm_kernel<<<NN / 8, 256>>>();
    knn_mma_kernel<<<dim3(NN / 128, 2), 256, KNN_SMEM>>>();
    knn_rescore_kernel<<<NN / 8, 256>>>();
    gcn1_gemm<<<NN / 32, 256>>>(W1);
    gather1<<<NN, CC>>>(b1);
    m2_kernel<<<NN / 8, 256>>>(W2);
    out_kernel<<<NN / 256, 256>>>(b2, out);
}